// round 10
// baseline (speedup 1.0000x reference)
#include <cuda_runtime.h>
#include <cuda_fp16.h>
#include <cstdint>

#define NN 100000
#define NE 3200000
#define DEG_SCALE 33554432.0f   // 2^25 fixed-point for packed degree
#define NBKT 64

// ---------------- scratch (device globals; no allocation allowed) ----------
__device__ __align__(16) unsigned long long g_pack[NN]; // {cnt<<40 | deg*2^25}
__device__ __align__(16) float g_dinv[NN];
__device__ __align__(16) int   g_cnt[NN];
__device__ __align__(16) int   g_off[NN];
__device__ __align__(16) int   g_cur[NN];
__device__ __align__(16) int   g_bsum[512];
__device__ __align__(16) int   g_bcnt[NBKT];   // degree-bucket histogram
__device__ __align__(16) int   g_bcur[NBKT];   // degree-bucket cursors
__device__ __align__(16) int   g_perm[NN];     // degree-sorted node order
__device__ int g_is64;

// CSR payload: (src << 15) | fp16bits(norm); norm >= 0 so 15 bits suffice
__device__ __align__(16) unsigned g_emeta[NE];

__device__ __align__(16) __half g_t1h[NN * 32]; // x @ W1 (fp16)
__device__ __align__(16) __half g_h1h[NN * 32]; // elu layer-1 out (fp16)
__device__ __align__(16) float  g_s2 [NN * 32]; // A @ h1 (fp32)
__device__ __align__(16) __half g_h2h[NN * 64]; // elu layer-2 out (fp16)
__device__ __align__(16) float  g_s3 [NN * 64]; // A @ h2 (fp32)

// ---------------- init + dtype detect (merged) -----------------------------
__global__ void k_init(const int* __restrict__ ei32, int n) {
    if (blockIdx.x == 0) {
        __shared__ int cnt;
        if (threadIdx.x == 0) cnt = 0;
        __syncthreads();
        int zeros = 0;
        for (int i = threadIdx.x; i < 1024; i += blockDim.x)
            if (ei32[2 * i + 1] == 0) zeros++;
        atomicAdd(&cnt, zeros);
        __syncthreads();
        if (threadIdx.x == 0) g_is64 = (cnt > 900) ? 1 : 0;
        if (threadIdx.x < NBKT) {
            g_bcnt[threadIdx.x] = 0;
            g_bcur[threadIdx.x] = 0;
        }
    }
    int i = blockIdx.x * blockDim.x + threadIdx.x;
    if (i < n) g_pack[i] = (unsigned long long)DEG_SCALE;  // deg=1 (self), cnt=0
}

__device__ __forceinline__ void load_edge(const int* __restrict__ ei32,
                                          int e, int E, int n, int& r, int& c) {
    if (g_is64) {
        r = ei32[2 * (long long)e];
        c = ei32[2 * ((long long)E + e)];
    } else {
        r = ei32[e];
        c = ei32[E + e];
    }
    if ((unsigned)r >= (unsigned)n) r = 0;
    if ((unsigned)c >= (unsigned)n) c = 0;
}

__global__ void k_prep(const int* __restrict__ ei32,
                       const float* __restrict__ ea, int E, int n) {
    int e = blockIdx.x * blockDim.x + threadIdx.x;
    if (e >= E) return;
    int c;
    if (g_is64) c = ei32[2 * ((long long)E + e)];
    else        c = ei32[E + e];
    if ((unsigned)c >= (unsigned)n) c = 0;
    const unsigned long long add =
        (1ULL << 40) | (unsigned long long)(fmaxf(ea[e], 0.f) * DEG_SCALE + 0.5f);
    atomicAdd(&g_pack[c], add);
}

__global__ void k_dinv(int n) {
    int i = blockIdx.x * blockDim.x + threadIdx.x;
    if (i >= n) return;
    const unsigned long long p = g_pack[i];
    const int cnt = (int)(p >> 40);
    g_cnt[i] = cnt;
    const float d = (float)(p & 0xFFFFFFFFFFULL) * (1.0f / DEG_SCALE);
    g_dinv[i] = (d > 0.0f) ? rsqrtf(fmaxf(d, 1e-30f)) : 0.0f;
    atomicAdd(&g_bcnt[min(cnt >> 1, NBKT - 1)], 1);
}

// ---------------- scan of g_cnt -> g_off/g_cur + bucket scan ---------------
__global__ void k_scan1(int n) {
    __shared__ int sh[256];
    const int t = threadIdx.x;
    const int i = blockIdx.x * 256 + t;
    int v = (i < n) ? g_cnt[i] : 0;
    sh[t] = v;
    __syncthreads();
    for (int d = 1; d < 256; d <<= 1) {
        int u = (t >= d) ? sh[t - d] : 0;
        __syncthreads();
        sh[t] += u;
        __syncthreads();
    }
    if (i < n) g_off[i] = sh[t] - v;
    if (t == 255) g_bsum[blockIdx.x] = sh[255];
}

__global__ void k_scan2(int nb) {
    __shared__ int sh[512];
    const int t = threadIdx.x;
    int v = (t < nb) ? g_bsum[t] : 0;
    sh[t] = v;
    __syncthreads();
    for (int d = 1; d < 512; d <<= 1) {
        int u = (t >= d) ? sh[t - d] : 0;
        __syncthreads();
        sh[t] += u;
        __syncthreads();
    }
    if (t < nb) g_bsum[t] = sh[t] - v;
    // serial exclusive scan of the 64 degree buckets (thread 0; trivial)
    if (t == 0) {
        int acc = 0;
        for (int bkt = 0; bkt < NBKT; bkt++) {
            const int c = g_bcnt[bkt];
            g_bcur[bkt] = acc;
            acc += c;
        }
    }
}

__global__ void k_scan3(int n) {
    int i = blockIdx.x * 256 + threadIdx.x;
    if (i >= n) return;
    const int o = g_off[i] + g_bsum[blockIdx.x];
    g_off[i] = o;
    g_cur[i] = o;
    const int bkt = min(g_cnt[i] >> 1, NBKT - 1);
    const int pos = atomicAdd(&g_bcur[bkt], 1);
    g_perm[pos] = i;
}

// ---------------- CSR fill: meta = (src<<15) | halfbits(norm>=0) -----------
__global__ void k_fill(const int* __restrict__ ei32,
                       const float* __restrict__ ea, int E, int n) {
    int e = blockIdx.x * blockDim.x + threadIdx.x;
    if (e >= E) return;
    int r, c;
    load_edge(ei32, e, E, n, r, c);
    const int pos = atomicAdd(&g_cur[c], 1);
    const float w = fmaxf(g_dinv[r] * ea[e] * g_dinv[c], 0.f);
    const unsigned hb = (unsigned)__half_as_ushort(__float2half(w)) & 0x7FFFu;
    g_emeta[pos] = ((unsigned)r << 15) | hb;
}

// ---------------- register-tiled GEMM with fused epilogue -------------------
// 256 threads; thread tile = 4 nodes x 4 fouts; X staged transposed in smem.
template <int FIN, int FOUT, bool BIAS, bool ELU, bool WF, bool WH>
__global__ void k_gemm(const float* __restrict__ X, const float* __restrict__ W,
                       const float* __restrict__ b, float* __restrict__ Yf,
                       __half* __restrict__ Yh, int n) {
    constexpr int BX   = FOUT / 4;
    constexpr int BY   = 256 / BX;
    constexpr int NPB  = BY * 4;
    constexpr int KC   = 32;
    constexpr int XSTR = NPB + 1;

    __shared__ float Xs[KC * XSTR];
    __shared__ float Ws[KC * FOUT];

    const int tid = threadIdx.x;
    const int tx = tid % BX;
    const int ty = tid / BX;
    const int node0 = blockIdx.x * NPB;

    float acc[4][4] = {};

    for (int ck = 0; ck < FIN; ck += KC) {
#pragma unroll
        for (int t = 0; t < NPB * KC / 256; t++) {
            const int idx = t * 256 + tid;
            const int ln = idx / KC;
            const int k  = idx % KC;
            const int node = node0 + ln;
            Xs[k * XSTR + ln] = (node < n) ? X[(size_t)node * FIN + ck + k] : 0.f;
        }
#pragma unroll
        for (int t = 0; t < KC * FOUT / 256; t++) {
            const int idx = t * 256 + tid;
            Ws[idx] = W[(size_t)(ck + idx / FOUT) * FOUT + (idx % FOUT)];
        }
        __syncthreads();

#pragma unroll
        for (int k = 0; k < KC; k++) {
            const float4 wv = *(const float4*)&Ws[k * FOUT + tx * 4];
#pragma unroll
            for (int j = 0; j < 4; j++) {
                const float xv = Xs[k * XSTR + ty * 4 + j];
                acc[j][0] += xv * wv.x;
                acc[j][1] += xv * wv.y;
                acc[j][2] += xv * wv.z;
                acc[j][3] += xv * wv.w;
            }
        }
        __syncthreads();
    }

    float4 bv = make_float4(0.f, 0.f, 0.f, 0.f);
    if (BIAS) bv = *(const float4*)&b[tx * 4];

#pragma unroll
    for (int j = 0; j < 4; j++) {
        const int node = node0 + ty * 4 + j;
        if (node >= n) continue;
        float o0 = acc[j][0] + bv.x;
        float o1 = acc[j][1] + bv.y;
        float o2 = acc[j][2] + bv.z;
        float o3 = acc[j][3] + bv.w;
        if (ELU) {
            o0 = (o0 > 0.f) ? o0 : expm1f(o0);
            o1 = (o1 > 0.f) ? o1 : expm1f(o1);
            o2 = (o2 > 0.f) ? o2 : expm1f(o2);
            o3 = (o3 > 0.f) ? o3 : expm1f(o3);
        }
        if (WF) {
            float4 ov; ov.x = o0; ov.y = o1; ov.z = o2; ov.w = o3;
            *(float4*)(Yf + (size_t)node * FOUT + tx * 4) = ov;
        }
        if (WH) {
            __half2* hp = (__half2*)(Yh + (size_t)node * FOUT + tx * 4);
            hp[0] = __floats2half2_rn(o0, o1);
            hp[1] = __floats2half2_rn(o2, o3);
        }
    }
}

// ---------------- fused CSR aggregate (degree-balanced via g_perm) ----------
// out[i] = sum_{e in seg(i)} gh[src(e)]*norm(e) + gh[i]*dinv[i]^2 (+b, elu)
// F/8 lanes per node, 16B gathers, 4B packed meta, fp32 accumulation.
template <int F, bool BE, bool WF, bool WH>
__global__ void k_agg(const __half* __restrict__ gh, const float* __restrict__ b,
                      float* __restrict__ outf, __half* __restrict__ outh, int n) {
    constexpr int LPE = F / 8;
    const long long tid = (long long)blockIdx.x * blockDim.x + threadIdx.x;
    const int gid = (int)(tid / LPE);
    const int s = (int)(tid % LPE);
    if (gid >= n) return;
    const int node = g_perm[gid];

    const __half* __restrict__ tbl = gh + s * 8;
    const int base = g_off[node];
    const int deg  = g_cnt[node];

    float a0 = 0.f, a1 = 0.f, a2 = 0.f, a3 = 0.f;
    float a4 = 0.f, a5 = 0.f, a6 = 0.f, a7 = 0.f;
    int k = 0;
#define GATH(MT)                                                               \
    {                                                                          \
        const float w_ =                                                       \
            __half2float(__ushort_as_half((unsigned short)((MT) & 0x7FFFu)));  \
        const uint4 raw_ =                                                     \
            *(const uint4*)(tbl + (size_t)((MT) >> 15) * F);                   \
        const float2 p0_ = __half22float2(*(const __half2*)&raw_.x);           \
        const float2 p1_ = __half22float2(*(const __half2*)&raw_.y);           \
        const float2 p2_ = __half22float2(*(const __half2*)&raw_.z);           \
        const float2 p3_ = __half22float2(*(const __half2*)&raw_.w);           \
        a0 += p0_.x * w_; a1 += p0_.y * w_;                                    \
        a2 += p1_.x * w_; a3 += p1_.y * w_;                                    \
        a4 += p2_.x * w_; a5 += p2_.y * w_;                                    \
        a6 += p3_.x * w_; a7 += p3_.y * w_;                                    \
    }
    for (; k + 4 <= deg; k += 4) {
        const unsigned m0 = g_emeta[base + k],     m1 = g_emeta[base + k + 1];
        const unsigned m2 = g_emeta[base + k + 2], m3 = g_emeta[base + k + 3];
        GATH(m0) GATH(m1) GATH(m2) GATH(m3)
    }
    for (; k < deg; k++) {
        const unsigned m0 = g_emeta[base + k];
        GATH(m0)
    }
#undef GATH

    // self-loop
    float dv = g_dinv[node]; dv *= dv;
    {
        const uint4 raw = *(const uint4*)(tbl + (size_t)node * F);
        const float2 p0 = __half22float2(*(const __half2*)&raw.x);
        const float2 p1 = __half22float2(*(const __half2*)&raw.y);
        const float2 p2 = __half22float2(*(const __half2*)&raw.z);
        const float2 p3 = __half22float2(*(const __half2*)&raw.w);
        a0 += p0.x * dv; a1 += p0.y * dv;
        a2 += p1.x * dv; a3 += p1.y * dv;
        a4 += p2.x * dv; a5 += p2.y * dv;
        a6 += p3.x * dv; a7 += p3.y * dv;
    }
    if (BE) {
        a0 += b[s * 8 + 0]; a1 += b[s * 8 + 1];
        a2 += b[s * 8 + 2]; a3 += b[s * 8 + 3];
        a4 += b[s * 8 + 4]; a5 += b[s * 8 + 5];
        a6 += b[s * 8 + 6]; a7 += b[s * 8 + 7];
        a0 = (a0 > 0.f) ? a0 : expm1f(a0);
        a1 = (a1 > 0.f) ? a1 : expm1f(a1);
        a2 = (a2 > 0.f) ? a2 : expm1f(a2);
        a3 = (a3 > 0.f) ? a3 : expm1f(a3);
        a4 = (a4 > 0.f) ? a4 : expm1f(a4);
        a5 = (a5 > 0.f) ? a5 : expm1f(a5);
        a6 = (a6 > 0.f) ? a6 : expm1f(a6);
        a7 = (a7 > 0.f) ? a7 : expm1f(a7);
    }
    if (WF) {
        float4 o0; o0.x = a0; o0.y = a1; o0.z = a2; o0.w = a3;
        float4 o1; o1.x = a4; o1.y = a5; o1.z = a6; o1.w = a7;
        float4* fp = (float4*)(outf + (size_t)node * F + s * 8);
        fp[0] = o0; fp[1] = o1;
    }
    if (WH) {
        __half2* hp = (__half2*)(outh + (size_t)node * F + s * 8);
        hp[0] = __floats2half2_rn(a0, a1);
        hp[1] = __floats2half2_rn(a2, a3);
        hp[2] = __floats2half2_rn(a4, a5);
        hp[3] = __floats2half2_rn(a6, a7);
    }
}

// ---------------- launch ---------------------------------------------------
static inline int cdiv(long long a, int b) { return (int)((a + b - 1) / b); }

extern "C" void kernel_launch(void* const* d_in, const int* in_sizes, int n_in,
                              void* d_out, int out_size) {
    const float* x  = (const float*)d_in[0];
    const int*   ei = (const int*)d_in[1];
    const float* ea = (const float*)d_in[2];
    const float* W1 = (const float*)d_in[3];
    const float* b1 = (const float*)d_in[4];
    const float* W2 = (const float*)d_in[5];
    const float* b2 = (const float*)d_in[6];
    const float* W3 = (const float*)d_in[7];
    const float* b3 = (const float*)d_in[8];
    float* out = (float*)d_out;

    const int n = in_sizes[0] / 128;   // 100000
    const int E = in_sizes[2];         // 3200000

    void *p_t1h, *p_h1h, *p_s2, *p_h2h, *p_s3;
    cudaGetSymbolAddress(&p_t1h, g_t1h);
    cudaGetSymbolAddress(&p_h1h, g_h1h);
    cudaGetSymbolAddress(&p_s2,  g_s2);
    cudaGetSymbolAddress(&p_h2h, g_h2h);
    cudaGetSymbolAddress(&p_s3,  g_s3);

    const int T = 256;
    const int nb = cdiv(n, 256);

    // --- prep: degrees, dinv, degree buckets, CSR build ---
    k_init<<<cdiv(n, T), T>>>(ei, n);
    k_prep<<<cdiv(E, T), T>>>(ei, ea, E, n);
    k_dinv<<<cdiv(n, T), T>>>(n);
    k_scan1<<<nb, 256>>>(n);
    k_scan2<<<1, 512>>>(nb);
    k_scan3<<<nb, 256>>>(n);
    k_fill<<<cdiv(E, T), T>>>(ei, ea, E, n);

    // --- layer 1: t1 = x@W1 ; h1 = elu(A t1 + b1) ---
    k_gemm<128, 32, false, false, false, true><<<cdiv(n, 128), 256>>>(
        x, W1, nullptr, nullptr, (__half*)p_t1h, n);
    k_agg<32, true, false, true><<<cdiv((long long)n * 4, T), T>>>(
        (const __half*)p_t1h, b1, nullptr, (__half*)p_h1h, n);

    // --- layer 2: s2 = A h1 ; h2 = elu(s2@W2 + b2) ---
    k_agg<32, false, true, false><<<cdiv((long long)n * 4, T), T>>>(
        (const __half*)p_h1h, nullptr, (float*)p_s2, nullptr, n);
    k_gemm<32, 64, true, true, false, true><<<cdiv(n, 64), 256>>>(
        (const float*)p_s2, W2, b2, nullptr, (__half*)p_h2h, n);

    // --- layer 3: s3 = A h2 ; out = s3@W3 + b3 ---
    k_agg<64, false, true, false><<<cdiv((long long)n * 8, T), T>>>(
        (const __half*)p_h2h, nullptr, (float*)p_s3, nullptr, n);
    k_gemm<64, 128, true, false, true, false><<<cdiv(n, 32), 256>>>(
        (const float*)p_s3, W3, b3, out, nullptr, n);
}

// round 11
// speedup vs baseline: 1.0918x; 1.0918x over previous
#include <cuda_runtime.h>
#include <cuda_fp16.h>
#include <cstdint>

#define NN 100000
#define NE 3200000
#define DEG_SCALE 33554432.0f   // 2^25 fixed-point for packed degree

// ---------------- scratch (device globals; no allocation allowed) ----------
__device__ __align__(16) unsigned long long g_pack[NN]; // {cnt<<40 | deg*2^25}
__device__ __align__(16) float g_dinv[NN];
__device__ __align__(16) int   g_cnt[NN];
__device__ __align__(16) int   g_off[NN];
__device__ __align__(16) int   g_cur[NN];
__device__ __align__(16) int   g_bsum[512];
__device__ int g_is64;

__device__ __align__(16) uint2 g_edge[NE];      // CSR: {src, fp32 w=dinv[src]*ea}

__device__ __align__(16) __half g_t1h[NN * 32]; // x @ W1 (fp16)
__device__ __align__(16) __half g_h1h[NN * 32]; // elu layer-1 out (fp16)
__device__ __align__(16) float  g_s2 [NN * 32]; // A @ h1 (fp32)
__device__ __align__(16) __half g_h2h[NN * 64]; // elu layer-2 out (fp16)
__device__ __align__(16) float  g_s3 [NN * 64]; // A @ h2 (fp32)

// ---------------- init + dtype detect (merged) -----------------------------
__global__ void k_init(const int* __restrict__ ei32, int n) {
    if (blockIdx.x == 0) {
        __shared__ int cnt;
        if (threadIdx.x == 0) cnt = 0;
        __syncthreads();
        int zeros = 0;
        for (int i = threadIdx.x; i < 1024; i += blockDim.x)
            if (ei32[2 * i + 1] == 0) zeros++;
        atomicAdd(&cnt, zeros);
        __syncthreads();
        if (threadIdx.x == 0) g_is64 = (cnt > 900) ? 1 : 0;
    }
    int i = blockIdx.x * blockDim.x + threadIdx.x;
    if (i < n) g_pack[i] = (unsigned long long)DEG_SCALE;  // deg=1 (self), cnt=0
}

__device__ __forceinline__ void load_edge(const int* __restrict__ ei32,
                                          int e, int E, int n, int& r, int& c) {
    if (g_is64) {
        r = ei32[2 * (long long)e];
        c = ei32[2 * ((long long)E + e)];
    } else {
        r = ei32[e];
        c = ei32[E + e];
    }
    if ((unsigned)r >= (unsigned)n) r = 0;
    if ((unsigned)c >= (unsigned)n) c = 0;
}

__global__ void k_prep(const int* __restrict__ ei32,
                       const float* __restrict__ ea, int E, int n) {
    int e = blockIdx.x * blockDim.x + threadIdx.x;
    if (e >= E) return;
    int c;
    if (g_is64) c = ei32[2 * ((long long)E + e)];
    else        c = ei32[E + e];
    if ((unsigned)c >= (unsigned)n) c = 0;
    const unsigned long long add =
        (1ULL << 40) | (unsigned long long)(fmaxf(ea[e], 0.f) * DEG_SCALE + 0.5f);
    atomicAdd(&g_pack[c], add);
}

// ---------------- scan1 (+ dinv decode, merged) -----------------------------
__global__ void k_scan1(int n) {
    __shared__ int sh[256];
    const int t = threadIdx.x;
    const int i = blockIdx.x * 256 + t;
    int v = 0;
    if (i < n) {
        const unsigned long long p = g_pack[i];
        v = (int)(p >> 40);
        g_cnt[i] = v;
        const float d = (float)(p & 0xFFFFFFFFFFULL) * (1.0f / DEG_SCALE);
        g_dinv[i] = (d > 0.0f) ? rsqrtf(fmaxf(d, 1e-30f)) : 0.0f;
    }
    sh[t] = v;
    __syncthreads();
    for (int d = 1; d < 256; d <<= 1) {
        int u = (t >= d) ? sh[t - d] : 0;
        __syncthreads();
        sh[t] += u;
        __syncthreads();
    }
    if (i < n) g_off[i] = sh[t] - v;
    if (t == 255) g_bsum[blockIdx.x] = sh[255];
}

__global__ void k_scan2(int nb) {
    __shared__ int sh[512];
    const int t = threadIdx.x;
    int v = (t < nb) ? g_bsum[t] : 0;
    sh[t] = v;
    __syncthreads();
    for (int d = 1; d < 512; d <<= 1) {
        int u = (t >= d) ? sh[t - d] : 0;
        __syncthreads();
        sh[t] += u;
        __syncthreads();
    }
    if (t < nb) g_bsum[t] = sh[t] - v;
}

__global__ void k_scan3(int n) {
    int i = blockIdx.x * 256 + threadIdx.x;
    if (i < n) {
        const int o = g_off[i] + g_bsum[blockIdx.x];
        g_off[i] = o;
        g_cur[i] = o;
    }
}

// ---------------- CSR fill: w = dinv[src]*ea (dst factor applied in agg) ---
__global__ void k_fill(const int* __restrict__ ei32,
                       const float* __restrict__ ea, int E, int n) {
    int e = blockIdx.x * blockDim.x + threadIdx.x;
    if (e >= E) return;
    int r, c;
    load_edge(ei32, e, E, n, r, c);
    const int pos = atomicAdd(&g_cur[c], 1);
    const float w = g_dinv[r] * ea[e];
    g_edge[pos] = make_uint2((unsigned)r, __float_as_uint(w));
}

// ---------------- register-tiled GEMM with fused epilogue -------------------
// 256 threads; thread tile = 4 nodes x 4 fouts; X staged transposed in smem.
template <int FIN, int FOUT, bool BIAS, bool ELU, bool WF, bool WH>
__global__ void k_gemm(const float* __restrict__ X, const float* __restrict__ W,
                       const float* __restrict__ b, float* __restrict__ Yf,
                       __half* __restrict__ Yh, int n) {
    constexpr int BX   = FOUT / 4;
    constexpr int BY   = 256 / BX;
    constexpr int NPB  = BY * 4;
    constexpr int KC   = 32;
    constexpr int XSTR = NPB + 1;

    __shared__ float Xs[KC * XSTR];
    __shared__ float Ws[KC * FOUT];

    const int tid = threadIdx.x;
    const int tx = tid % BX;
    const int ty = tid / BX;
    const int node0 = blockIdx.x * NPB;

    float acc[4][4] = {};

    for (int ck = 0; ck < FIN; ck += KC) {
#pragma unroll
        for (int t = 0; t < NPB * KC / 256; t++) {
            const int idx = t * 256 + tid;
            const int ln = idx / KC;
            const int k  = idx % KC;
            const int node = node0 + ln;
            Xs[k * XSTR + ln] = (node < n) ? X[(size_t)node * FIN + ck + k] : 0.f;
        }
#pragma unroll
        for (int t = 0; t < KC * FOUT / 256; t++) {
            const int idx = t * 256 + tid;
            Ws[idx] = W[(size_t)(ck + idx / FOUT) * FOUT + (idx % FOUT)];
        }
        __syncthreads();

#pragma unroll
        for (int k = 0; k < KC; k++) {
            const float4 wv = *(const float4*)&Ws[k * FOUT + tx * 4];
#pragma unroll
            for (int j = 0; j < 4; j++) {
                const float xv = Xs[k * XSTR + ty * 4 + j];
                acc[j][0] += xv * wv.x;
                acc[j][1] += xv * wv.y;
                acc[j][2] += xv * wv.z;
                acc[j][3] += xv * wv.w;
            }
        }
        __syncthreads();
    }

    float4 bv = make_float4(0.f, 0.f, 0.f, 0.f);
    if (BIAS) bv = *(const float4*)&b[tx * 4];

#pragma unroll
    for (int j = 0; j < 4; j++) {
        const int node = node0 + ty * 4 + j;
        if (node >= n) continue;
        float o0 = acc[j][0] + bv.x;
        float o1 = acc[j][1] + bv.y;
        float o2 = acc[j][2] + bv.z;
        float o3 = acc[j][3] + bv.w;
        if (ELU) {
            o0 = (o0 > 0.f) ? o0 : expm1f(o0);
            o1 = (o1 > 0.f) ? o1 : expm1f(o1);
            o2 = (o2 > 0.f) ? o2 : expm1f(o2);
            o3 = (o3 > 0.f) ? o3 : expm1f(o3);
        }
        if (WF) {
            float4 ov; ov.x = o0; ov.y = o1; ov.z = o2; ov.w = o3;
            *(float4*)(Yf + (size_t)node * FOUT + tx * 4) = ov;
        }
        if (WH) {
            __half2* hp = (__half2*)(Yh + (size_t)node * FOUT + tx * 4);
            hp[0] = __floats2half2_rn(o0, o1);
            hp[1] = __floats2half2_rn(o2, o3);
        }
    }
}

// ---------------- fused CSR aggregate ---------------------------------------
// out[i] = dinv[i]*sum_{e in seg(i)} gh[src(e)]*w(e) + gh[i]*dinv[i]^2 (+b,elu)
// F/8 lanes per node; each lane owns 8 halfs (one 16B load per edge).
template <int F, bool BE, bool WF, bool WH>
__global__ void k_agg(const __half* __restrict__ gh, const float* __restrict__ b,
                      float* __restrict__ outf, __half* __restrict__ outh, int n) {
    constexpr int LPE = F / 8;
    const long long tid = (long long)blockIdx.x * blockDim.x + threadIdx.x;
    const int node = (int)(tid / LPE);
    const int s = (int)(tid % LPE);
    if (node >= n) return;

    const __half* __restrict__ tbl = gh + s * 8;
    const int base = g_off[node];
    const int deg  = g_cnt[node];

    float a0 = 0.f, a1 = 0.f, a2 = 0.f, a3 = 0.f;
    float a4 = 0.f, a5 = 0.f, a6 = 0.f, a7 = 0.f;
    int k = 0;
#define GATH(ED)                                                               \
    {                                                                          \
        const float w_ = __uint_as_float((ED).y);                              \
        const uint4 raw_ = *(const uint4*)(tbl + (size_t)(ED).x * F);          \
        const float2 p0_ = __half22float2(*(const __half2*)&raw_.x);           \
        const float2 p1_ = __half22float2(*(const __half2*)&raw_.y);           \
        const float2 p2_ = __half22float2(*(const __half2*)&raw_.z);           \
        const float2 p3_ = __half22float2(*(const __half2*)&raw_.w);           \
        a0 += p0_.x * w_; a1 += p0_.y * w_;                                    \
        a2 += p1_.x * w_; a3 += p1_.y * w_;                                    \
        a4 += p2_.x * w_; a5 += p2_.y * w_;                                    \
        a6 += p3_.x * w_; a7 += p3_.y * w_;                                    \
    }
    for (; k + 4 <= deg; k += 4) {
        const uint2 e0 = g_edge[base + k],     e1 = g_edge[base + k + 1];
        const uint2 e2 = g_edge[base + k + 2], e3 = g_edge[base + k + 3];
        GATH(e0) GATH(e1) GATH(e2) GATH(e3)
    }
    for (; k < deg; k++) {
        const uint2 e0 = g_edge[base + k];
        GATH(e0)
    }
#undef GATH

    // scale by dinv[dst]; self-loop term h[node]*dinv^2
    const float dn = g_dinv[node];
    {
        const uint4 raw = *(const uint4*)(tbl + (size_t)node * F);
        const float2 p0 = __half22float2(*(const __half2*)&raw.x);
        const float2 p1 = __half22float2(*(const __half2*)&raw.y);
        const float2 p2 = __half22float2(*(const __half2*)&raw.z);
        const float2 p3 = __half22float2(*(const __half2*)&raw.w);
        a0 = (a0 + p0.x * dn) * dn; a1 = (a1 + p0.y * dn) * dn;
        a2 = (a2 + p1.x * dn) * dn; a3 = (a3 + p1.y * dn) * dn;
        a4 = (a4 + p2.x * dn) * dn; a5 = (a5 + p2.y * dn) * dn;
        a6 = (a6 + p3.x * dn) * dn; a7 = (a7 + p3.y * dn) * dn;
    }
    if (BE) {
        a0 += b[s * 8 + 0]; a1 += b[s * 8 + 1];
        a2 += b[s * 8 + 2]; a3 += b[s * 8 + 3];
        a4 += b[s * 8 + 4]; a5 += b[s * 8 + 5];
        a6 += b[s * 8 + 6]; a7 += b[s * 8 + 7];
        a0 = (a0 > 0.f) ? a0 : expm1f(a0);
        a1 = (a1 > 0.f) ? a1 : expm1f(a1);
        a2 = (a2 > 0.f) ? a2 : expm1f(a2);
        a3 = (a3 > 0.f) ? a3 : expm1f(a3);
        a4 = (a4 > 0.f) ? a4 : expm1f(a4);
        a5 = (a5 > 0.f) ? a5 : expm1f(a5);
        a6 = (a6 > 0.f) ? a6 : expm1f(a6);
        a7 = (a7 > 0.f) ? a7 : expm1f(a7);
    }
    if (WF) {
        float4 o0; o0.x = a0; o0.y = a1; o0.z = a2; o0.w = a3;
        float4 o1; o1.x = a4; o1.y = a5; o1.z = a6; o1.w = a7;
        float4* fp = (float4*)(outf + (size_t)node * F + s * 8);
        fp[0] = o0; fp[1] = o1;
    }
    if (WH) {
        __half2* hp = (__half2*)(outh + (size_t)node * F + s * 8);
        hp[0] = __floats2half2_rn(a0, a1);
        hp[1] = __floats2half2_rn(a2, a3);
        hp[2] = __floats2half2_rn(a4, a5);
        hp[3] = __floats2half2_rn(a6, a7);
    }
}

// ---------------- launch ---------------------------------------------------
static inline int cdiv(long long a, int b) { return (int)((a + b - 1) / b); }

extern "C" void kernel_launch(void* const* d_in, const int* in_sizes, int n_in,
                              void* d_out, int out_size) {
    const float* x  = (const float*)d_in[0];
    const int*   ei = (const int*)d_in[1];
    const float* ea = (const float*)d_in[2];
    const float* W1 = (const float*)d_in[3];
    const float* b1 = (const float*)d_in[4];
    const float* W2 = (const float*)d_in[5];
    const float* b2 = (const float*)d_in[6];
    const float* W3 = (const float*)d_in[7];
    const float* b3 = (const float*)d_in[8];
    float* out = (float*)d_out;

    const int n = in_sizes[0] / 128;   // 100000
    const int E = in_sizes[2];         // 3200000

    void *p_t1h, *p_h1h, *p_s2, *p_h2h, *p_s3;
    cudaGetSymbolAddress(&p_t1h, g_t1h);
    cudaGetSymbolAddress(&p_h1h, g_h1h);
    cudaGetSymbolAddress(&p_s2,  g_s2);
    cudaGetSymbolAddress(&p_h2h, g_h2h);
    cudaGetSymbolAddress(&p_s3,  g_s3);

    const int T = 256;
    const int nb = cdiv(n, 256);

    // --- prep: degrees+dinv, scan, CSR fill (12 launches total) ---
    k_init<<<cdiv(n, T), T>>>(ei, n);
    k_prep<<<cdiv(E, T), T>>>(ei, ea, E, n);
    k_scan1<<<nb, 256>>>(n);
    k_scan2<<<1, 512>>>(nb);
    k_scan3<<<nb, 256>>>(n);
    k_fill<<<cdiv(E, T), T>>>(ei, ea, E, n);

    // --- layer 1: t1 = x@W1 ; h1 = elu(A t1 + b1) ---
    k_gemm<128, 32, false, false, false, true><<<cdiv(n, 128), 256>>>(
        x, W1, nullptr, nullptr, (__half*)p_t1h, n);
    k_agg<32, true, false, true><<<cdiv((long long)n * 4, T), T>>>(
        (const __half*)p_t1h, b1, nullptr, (__half*)p_h1h, n);

    // --- layer 2: s2 = A h1 ; h2 = elu(s2@W2 + b2) ---
    k_agg<32, false, true, false><<<cdiv((long long)n * 4, T), T>>>(
        (const __half*)p_h1h, nullptr, (float*)p_s2, nullptr, n);
    k_gemm<32, 64, true, true, false, true><<<cdiv(n, 64), 256>>>(
        (const float*)p_s2, W2, b2, nullptr, (__half*)p_h2h, n);

    // --- layer 3: s3 = A h2 ; out = s3@W3 + b3 ---
    k_agg<64, false, true, false><<<cdiv((long long)n * 8, T), T>>>(
        (const __half*)p_h2h, nullptr, (float*)p_s3, nullptr, n);
    k_gemm<64, 128, true, false, true, false><<<cdiv(n, 32), 256>>>(
        (const float*)p_s3, W3, b3, out, nullptr, n);
}

// round 12
// speedup vs baseline: 1.1433x; 1.0472x over previous
#include <cuda_runtime.h>
#include <cuda_fp16.h>
#include <cstdint>

#define NN 100000
#define NE 3200000
#define DEG_SCALE 33554432.0f   // 2^25 fixed-point for packed degree

// ---------------- scratch (device globals; no allocation allowed) ----------
__device__ __align__(16) unsigned long long g_pack[NN]; // {cnt<<40 | deg*2^25}
__device__ __align__(16) float g_dinv[NN];
__device__ __align__(16) int   g_cnt[NN];
__device__ __align__(16) int   g_off[NN];
__device__ __align__(16) int   g_cur[NN];
__device__ __align__(16) int   g_bsum[512];
__device__ int g_is64;

__device__ __align__(16) uint2 g_edge[NE];      // CSR: {src, fp32 w=dinv[src]*ea}

__device__ __align__(16) __half g_t1h[NN * 32]; // x @ W1 (fp16)
__device__ __align__(16) __half g_h1h[NN * 32]; // elu layer-1 out (fp16)
__device__ __align__(16) float  g_s2 [NN * 32]; // A @ h1 (fp32)
__device__ __align__(16) __half g_h2h[NN * 64]; // elu layer-2 out (fp16)
__device__ __align__(16) float  g_s3 [NN * 64]; // A @ h2 (fp32)

// ---------------- init + dtype detect (merged) -----------------------------
__global__ void k_init(const int* __restrict__ ei32, int n) {
    if (blockIdx.x == 0) {
        __shared__ int cnt;
        if (threadIdx.x == 0) cnt = 0;
        __syncthreads();
        int zeros = 0;
        for (int i = threadIdx.x; i < 1024; i += blockDim.x)
            if (ei32[2 * i + 1] == 0) zeros++;
        atomicAdd(&cnt, zeros);
        __syncthreads();
        if (threadIdx.x == 0) g_is64 = (cnt > 900) ? 1 : 0;
    }
    int i = blockIdx.x * blockDim.x + threadIdx.x;
    if (i < n) g_pack[i] = (unsigned long long)DEG_SCALE;  // deg=1 (self), cnt=0
}

__device__ __forceinline__ void load_edge(const int* __restrict__ ei32,
                                          int e, int E, int n, int& r, int& c) {
    if (g_is64) {
        r = ei32[2 * (long long)e];
        c = ei32[2 * ((long long)E + e)];
    } else {
        r = ei32[e];
        c = ei32[E + e];
    }
    if ((unsigned)r >= (unsigned)n) r = 0;
    if ((unsigned)c >= (unsigned)n) c = 0;
}

__global__ void k_prep(const int* __restrict__ ei32,
                       const float* __restrict__ ea, int E, int n) {
    int e = blockIdx.x * blockDim.x + threadIdx.x;
    if (e >= E) return;
    int c;
    if (g_is64) c = ei32[2 * ((long long)E + e)];
    else        c = ei32[E + e];
    if ((unsigned)c >= (unsigned)n) c = 0;
    const unsigned long long add =
        (1ULL << 40) | (unsigned long long)(fmaxf(ea[e], 0.f) * DEG_SCALE + 0.5f);
    atomicAdd(&g_pack[c], add);
}

// ---------------- scan1 (+ dinv decode, merged) -----------------------------
__global__ void k_scan1(int n) {
    __shared__ int sh[256];
    const int t = threadIdx.x;
    const int i = blockIdx.x * 256 + t;
    int v = 0;
    if (i < n) {
        const unsigned long long p = g_pack[i];
        v = (int)(p >> 40);
        g_cnt[i] = v;
        const float d = (float)(p & 0xFFFFFFFFFFULL) * (1.0f / DEG_SCALE);
        g_dinv[i] = (d > 0.0f) ? rsqrtf(fmaxf(d, 1e-30f)) : 0.0f;
    }
    sh[t] = v;
    __syncthreads();
    for (int d = 1; d < 256; d <<= 1) {
        int u = (t >= d) ? sh[t - d] : 0;
        __syncthreads();
        sh[t] += u;
        __syncthreads();
    }
    if (i < n) g_off[i] = sh[t] - v;
    if (t == 255) g_bsum[blockIdx.x] = sh[255];
}

__global__ void k_scan2(int nb) {
    __shared__ int sh[512];
    const int t = threadIdx.x;
    int v = (t < nb) ? g_bsum[t] : 0;
    sh[t] = v;
    __syncthreads();
    for (int d = 1; d < 512; d <<= 1) {
        int u = (t >= d) ? sh[t - d] : 0;
        __syncthreads();
        sh[t] += u;
        __syncthreads();
    }
    if (t < nb) g_bsum[t] = sh[t] - v;
}

__global__ void k_scan3(int n) {
    int i = blockIdx.x * 256 + threadIdx.x;
    if (i < n) {
        const int o = g_off[i] + g_bsum[blockIdx.x];
        g_off[i] = o;
        g_cur[i] = o;
    }
}

// ---------------- CSR fill: w = dinv[src]*ea (dst factor applied in agg) ---
__global__ void k_fill(const int* __restrict__ ei32,
                       const float* __restrict__ ea, int E, int n) {
    int e = blockIdx.x * blockDim.x + threadIdx.x;
    if (e >= E) return;
    int r, c;
    load_edge(ei32, e, E, n, r, c);
    const int pos = atomicAdd(&g_cur[c], 1);
    const float w = g_dinv[r] * ea[e];
    g_edge[pos] = make_uint2((unsigned)r, __float_as_uint(w));
}

// ---------------- register-tiled GEMM with fused epilogue -------------------
// 256 threads; thread tile = 4 nodes x 4 fouts; X staged transposed in smem.
template <int FIN, int FOUT, bool BIAS, bool ELU, bool WF, bool WH>
__global__ void k_gemm(const float* __restrict__ X, const float* __restrict__ W,
                       const float* __restrict__ b, float* __restrict__ Yf,
                       __half* __restrict__ Yh, int n) {
    constexpr int BX   = FOUT / 4;
    constexpr int BY   = 256 / BX;
    constexpr int NPB  = BY * 4;
    constexpr int KC   = 32;
    constexpr int XSTR = NPB + 1;

    __shared__ float Xs[KC * XSTR];
    __shared__ float Ws[KC * FOUT];

    const int tid = threadIdx.x;
    const int tx = tid % BX;
    const int ty = tid / BX;
    const int node0 = blockIdx.x * NPB;

    float acc[4][4] = {};

    for (int ck = 0; ck < FIN; ck += KC) {
#pragma unroll
        for (int t = 0; t < NPB * KC / 256; t++) {
            const int idx = t * 256 + tid;
            const int ln = idx / KC;
            const int k  = idx % KC;
            const int node = node0 + ln;
            Xs[k * XSTR + ln] = (node < n) ? X[(size_t)node * FIN + ck + k] : 0.f;
        }
#pragma unroll
        for (int t = 0; t < KC * FOUT / 256; t++) {
            const int idx = t * 256 + tid;
            Ws[idx] = W[(size_t)(ck + idx / FOUT) * FOUT + (idx % FOUT)];
        }
        __syncthreads();

#pragma unroll
        for (int k = 0; k < KC; k++) {
            const float4 wv = *(const float4*)&Ws[k * FOUT + tx * 4];
#pragma unroll
            for (int j = 0; j < 4; j++) {
                const float xv = Xs[k * XSTR + ty * 4 + j];
                acc[j][0] += xv * wv.x;
                acc[j][1] += xv * wv.y;
                acc[j][2] += xv * wv.z;
                acc[j][3] += xv * wv.w;
            }
        }
        __syncthreads();
    }

    float4 bv = make_float4(0.f, 0.f, 0.f, 0.f);
    if (BIAS) bv = *(const float4*)&b[tx * 4];

#pragma unroll
    for (int j = 0; j < 4; j++) {
        const int node = node0 + ty * 4 + j;
        if (node >= n) continue;
        float o0 = acc[j][0] + bv.x;
        float o1 = acc[j][1] + bv.y;
        float o2 = acc[j][2] + bv.z;
        float o3 = acc[j][3] + bv.w;
        if (ELU) {
            o0 = (o0 > 0.f) ? o0 : expm1f(o0);
            o1 = (o1 > 0.f) ? o1 : expm1f(o1);
            o2 = (o2 > 0.f) ? o2 : expm1f(o2);
            o3 = (o3 > 0.f) ? o3 : expm1f(o3);
        }
        if (WF) {
            float4 ov; ov.x = o0; ov.y = o1; ov.z = o2; ov.w = o3;
            *(float4*)(Yf + (size_t)node * FOUT + tx * 4) = ov;
        }
        if (WH) {
            __half2* hp = (__half2*)(Yh + (size_t)node * FOUT + tx * 4);
            hp[0] = __floats2half2_rn(o0, o1);
            hp[1] = __floats2half2_rn(o2, o3);
        }
    }
}

// ---------------- fused CSR aggregate ---------------------------------------
// out[i] = dinv[i]*sum_{e in seg(i)} gh[src(e)]*w(e) + gh[i]*dinv[i]^2 (+b,elu)
// F/8 lanes per node; each lane owns 8 halfs (one 16B load per edge).
template <int F, bool BE, bool WF, bool WH>
__global__ void k_agg(const __half* __restrict__ gh, const float* __restrict__ b,
                      float* __restrict__ outf, __half* __restrict__ outh, int n) {
    constexpr int LPE = F / 8;
    const long long tid = (long long)blockIdx.x * blockDim.x + threadIdx.x;
    const int node = (int)(tid / LPE);
    const int s = (int)(tid % LPE);
    if (node >= n) return;

    const __half* __restrict__ tbl = gh + s * 8;
    const int base = g_off[node];
    const int deg  = g_cnt[node];

    float a0 = 0.f, a1 = 0.f, a2 = 0.f, a3 = 0.f;
    float a4 = 0.f, a5 = 0.f, a6 = 0.f, a7 = 0.f;
    int k = 0;
#define GATH(ED)                                                               \
    {                                                                          \
        const float w_ = __uint_as_float((ED).y);                              \
        const uint4 raw_ = *(const uint4*)(tbl + (size_t)(ED).x * F);          \
        const float2 p0_ = __half22float2(*(const __half2*)&raw_.x);           \
        const float2 p1_ = __half22float2(*(const __half2*)&raw_.y);           \
        const float2 p2_ = __half22float2(*(const __half2*)&raw_.z);           \
        const float2 p3_ = __half22float2(*(const __half2*)&raw_.w);           \
        a0 += p0_.x * w_; a1 += p0_.y * w_;                                    \
        a2 += p1_.x * w_; a3 += p1_.y * w_;                                    \
        a4 += p2_.x * w_; a5 += p2_.y * w_;                                    \
        a6 += p3_.x * w_; a7 += p3_.y * w_;                                    \
    }
    for (; k + 4 <= deg; k += 4) {
        const uint2 e0 = g_edge[base + k],     e1 = g_edge[base + k + 1];
        const uint2 e2 = g_edge[base + k + 2], e3 = g_edge[base + k + 3];
        GATH(e0) GATH(e1) GATH(e2) GATH(e3)
    }
    for (; k < deg; k++) {
        const uint2 e0 = g_edge[base + k];
        GATH(e0)
    }
#undef GATH

    // scale by dinv[dst]; self-loop term h[node]*dinv^2
    const float dn = g_dinv[node];
    {
        const uint4 raw = *(const uint4*)(tbl + (size_t)node * F);
        const float2 p0 = __half22float2(*(const __half2*)&raw.x);
        const float2 p1 = __half22float2(*(const __half2*)&raw.y);
        const float2 p2 = __half22float2(*(const __half2*)&raw.z);
        const float2 p3 = __half22float2(*(const __half2*)&raw.w);
        a0 = (a0 + p0.x * dn) * dn; a1 = (a1 + p0.y * dn) * dn;
        a2 = (a2 + p1.x * dn) * dn; a3 = (a3 + p1.y * dn) * dn;
        a4 = (a4 + p2.x * dn) * dn; a5 = (a5 + p2.y * dn) * dn;
        a6 = (a6 + p3.x * dn) * dn; a7 = (a7 + p3.y * dn) * dn;
    }
    if (BE) {
        a0 += b[s * 8 + 0]; a1 += b[s * 8 + 1];
        a2 += b[s * 8 + 2]; a3 += b[s * 8 + 3];
        a4 += b[s * 8 + 4]; a5 += b[s * 8 + 5];
        a6 += b[s * 8 + 6]; a7 += b[s * 8 + 7];
        a0 = (a0 > 0.f) ? a0 : expm1f(a0);
        a1 = (a1 > 0.f) ? a1 : expm1f(a1);
        a2 = (a2 > 0.f) ? a2 : expm1f(a2);
        a3 = (a3 > 0.f) ? a3 : expm1f(a3);
        a4 = (a4 > 0.f) ? a4 : expm1f(a4);
        a5 = (a5 > 0.f) ? a5 : expm1f(a5);
        a6 = (a6 > 0.f) ? a6 : expm1f(a6);
        a7 = (a7 > 0.f) ? a7 : expm1f(a7);
    }
    if (WF) {
        float4 o0; o0.x = a0; o0.y = a1; o0.z = a2; o0.w = a3;
        float4 o1; o1.x = a4; o1.y = a5; o1.z = a6; o1.w = a7;
        float4* fp = (float4*)(outf + (size_t)node * F + s * 8);
        fp[0] = o0; fp[1] = o1;
    }
    if (WH) {
        __half2* hp = (__half2*)(outh + (size_t)node * F + s * 8);
        hp[0] = __floats2half2_rn(a0, a1);
        hp[1] = __floats2half2_rn(a2, a3);
        hp[2] = __floats2half2_rn(a4, a5);
        hp[3] = __floats2half2_rn(a6, a7);
    }
}

// ---------------- launch ---------------------------------------------------
static inline int cdiv(long long a, int b) { return (int)((a + b - 1) / b); }

// Lazy-created side stream + events (host resources only; no device memory).
static cudaStream_t s_side = nullptr;
static cudaEvent_t  s_evFork = nullptr, s_evJoin = nullptr;

extern "C" void kernel_launch(void* const* d_in, const int* in_sizes, int n_in,
                              void* d_out, int out_size) {
    const float* x  = (const float*)d_in[0];
    const int*   ei = (const int*)d_in[1];
    const float* ea = (const float*)d_in[2];
    const float* W1 = (const float*)d_in[3];
    const float* b1 = (const float*)d_in[4];
    const float* W2 = (const float*)d_in[5];
    const float* b2 = (const float*)d_in[6];
    const float* W3 = (const float*)d_in[7];
    const float* b3 = (const float*)d_in[8];
    float* out = (float*)d_out;

    const int n = in_sizes[0] / 128;   // 100000
    const int E = in_sizes[2];         // 3200000

    if (s_side == nullptr) {
        cudaStreamCreateWithFlags(&s_side, cudaStreamNonBlocking);
        cudaEventCreateWithFlags(&s_evFork, cudaEventDisableTiming);
        cudaEventCreateWithFlags(&s_evJoin, cudaEventDisableTiming);
    }

    void *p_t1h, *p_h1h, *p_s2, *p_h2h, *p_s3;
    cudaGetSymbolAddress(&p_t1h, g_t1h);
    cudaGetSymbolAddress(&p_h1h, g_h1h);
    cudaGetSymbolAddress(&p_s2,  g_s2);
    cudaGetSymbolAddress(&p_h2h, g_h2h);
    cudaGetSymbolAddress(&p_s3,  g_s3);

    const int T = 256;
    const int nb = cdiv(n, 256);

    // --- fork: GEMM1 (x@W1, independent of CSR prep) on side stream ---
    cudaEventRecord(s_evFork, 0);
    cudaStreamWaitEvent(s_side, s_evFork, 0);
    k_gemm<128, 32, false, false, false, true><<<cdiv(n, 128), 256, 0, s_side>>>(
        x, W1, nullptr, nullptr, (__half*)p_t1h, n);
    cudaEventRecord(s_evJoin, s_side);

    // --- prep: degrees+dinv, scan, CSR fill (main stream) ---
    k_init<<<cdiv(n, T), T>>>(ei, n);
    k_prep<<<cdiv(E, T), T>>>(ei, ea, E, n);
    k_scan1<<<nb, 256>>>(n);
    k_scan2<<<1, 512>>>(nb);
    k_scan3<<<nb, 256>>>(n);
    k_fill<<<cdiv(E, T), T>>>(ei, ea, E, n);

    // --- join: layer-1 agg needs both t1h (side) and CSR (main) ---
    cudaStreamWaitEvent(0, s_evJoin, 0);
    k_agg<32, true, false, true><<<cdiv((long long)n * 4, T), T>>>(
        (const __half*)p_t1h, b1, nullptr, (__half*)p_h1h, n);

    // --- layer 2: s2 = A h1 ; h2 = elu(s2@W2 + b2) ---
    k_agg<32, false, true, false><<<cdiv((long long)n * 4, T), T>>>(
        (const __half*)p_h1h, nullptr, (float*)p_s2, nullptr, n);
    k_gemm<32, 64, true, true, false, true><<<cdiv(n, 64), 256>>>(
        (const float*)p_s2, W2, b2, nullptr, (__half*)p_h2h, n);

    // --- layer 3: s3 = A h2 ; out = s3@W3 + b3 ---
    k_agg<64, false, true, false><<<cdiv((long long)n * 8, T), T>>>(
        (const __half*)p_h2h, nullptr, (float*)p_s3, nullptr, n);
    k_gemm<64, 128, true, false, true, false><<<cdiv(n, 32), 256>>>(
        (const float*)p_s3, W3, b3, out, nullptr, n);
}

// round 13
// speedup vs baseline: 1.1482x; 1.0043x over previous
#include <cuda_runtime.h>
#include <cuda_fp16.h>
#include <cstdint>

#define NN 100000
#define NE 3200000
#define DEG_SCALE 33554432.0f   // 2^25 fixed-point for packed degree

// ---------------- scratch (device globals; no allocation allowed) ----------
__device__ __align__(16) unsigned long long g_pack[NN]; // {cnt<<40 | deg*2^25}
__device__ __align__(16) float g_dinv[NN];
__device__ __align__(16) int   g_cnt[NN];
__device__ __align__(16) int   g_off[NN];
__device__ __align__(16) int   g_cur[NN];
__device__ int g_total;
__device__ int g_is64;

__device__ __align__(16) uint2 g_edge[NE];      // CSR: {src, fp32 w=dinv[src]*ea}

__device__ __align__(16) __half g_t1h[NN * 32]; // x @ W1 (fp16)
__device__ __align__(16) __half g_h1h[NN * 32]; // elu layer-1 out (fp16)
__device__ __align__(16) float  g_s2 [NN * 32]; // A @ h1 (fp32)
__device__ __align__(16) __half g_h2h[NN * 64]; // elu layer-2 out (fp16)
__device__ __align__(16) float  g_s3 [NN * 64]; // A @ h2 (fp32)

// ---------------- init + dtype detect (merged) -----------------------------
__global__ void k_init(const int* __restrict__ ei32, int n) {
    if (blockIdx.x == 0) {
        __shared__ int cnt;
        if (threadIdx.x == 0) { cnt = 0; g_total = 0; }
        __syncthreads();
        int zeros = 0;
        for (int i = threadIdx.x; i < 1024; i += blockDim.x)
            if (ei32[2 * i + 1] == 0) zeros++;
        atomicAdd(&cnt, zeros);
        __syncthreads();
        if (threadIdx.x == 0) g_is64 = (cnt > 900) ? 1 : 0;
    }
    int i = blockIdx.x * blockDim.x + threadIdx.x;
    if (i < n) g_pack[i] = (unsigned long long)DEG_SCALE;  // deg=1 (self), cnt=0
}

__device__ __forceinline__ void load_edge(const int* __restrict__ ei32,
                                          int e, int E, int n, int& r, int& c) {
    if (g_is64) {
        r = ei32[2 * (long long)e];
        c = ei32[2 * ((long long)E + e)];
    } else {
        r = ei32[e];
        c = ei32[E + e];
    }
    if ((unsigned)r >= (unsigned)n) r = 0;
    if ((unsigned)c >= (unsigned)n) c = 0;
}

__global__ void k_prep(const int* __restrict__ ei32,
                       const float* __restrict__ ea, int E, int n) {
    int e = blockIdx.x * blockDim.x + threadIdx.x;
    if (e >= E) return;
    int c;
    if (g_is64) c = ei32[2 * ((long long)E + e)];
    else        c = ei32[E + e];
    if ((unsigned)c >= (unsigned)n) c = 0;
    const unsigned long long add =
        (1ULL << 40) | (unsigned long long)(fmaxf(ea[e], 0.f) * DEG_SCALE + 0.5f);
    atomicAdd(&g_pack[c], add);
}

// ---------------- assign: dinv decode + counter-based segment reservation ---
// Segment offsets need not be ordered by node id; reserve via one global
// counter (warp-aggregated REDUX+ATOMG). Replaces the 3-kernel scan.
__global__ void k_assign(int n) {
    int i = blockIdx.x * blockDim.x + threadIdx.x;
    if (i >= n) return;
    const unsigned long long p = g_pack[i];
    const int cnt = (int)(p >> 40);
    g_cnt[i] = cnt;
    const float d = (float)(p & 0xFFFFFFFFFFULL) * (1.0f / DEG_SCALE);
    g_dinv[i] = (d > 0.0f) ? rsqrtf(fmaxf(d, 1e-30f)) : 0.0f;
    const int pos = atomicAdd(&g_total, cnt);
    g_off[i] = pos;
    g_cur[i] = pos;
}

// ---------------- CSR fill: w = dinv[src]*ea (dst factor applied in agg) ---
__global__ void k_fill(const int* __restrict__ ei32,
                       const float* __restrict__ ea, int E, int n) {
    int e = blockIdx.x * blockDim.x + threadIdx.x;
    if (e >= E) return;
    int r, c;
    load_edge(ei32, e, E, n, r, c);
    const int pos = atomicAdd(&g_cur[c], 1);
    const float w = g_dinv[r] * ea[e];
    g_edge[pos] = make_uint2((unsigned)r, __float_as_uint(w));
}

// ---------------- register-tiled GEMM with fused epilogue -------------------
// 256 threads; thread tile = 4 nodes x 4 fouts; X staged transposed in smem.
template <int FIN, int FOUT, bool BIAS, bool ELU, bool WF, bool WH>
__global__ void k_gemm(const float* __restrict__ X, const float* __restrict__ W,
                       const float* __restrict__ b, float* __restrict__ Yf,
                       __half* __restrict__ Yh, int n) {
    constexpr int BX   = FOUT / 4;
    constexpr int BY   = 256 / BX;
    constexpr int NPB  = BY * 4;
    constexpr int KC   = 32;
    constexpr int XSTR = NPB + 1;

    __shared__ float Xs[KC * XSTR];
    __shared__ float Ws[KC * FOUT];

    const int tid = threadIdx.x;
    const int tx = tid % BX;
    const int ty = tid / BX;
    const int node0 = blockIdx.x * NPB;

    float acc[4][4] = {};

    for (int ck = 0; ck < FIN; ck += KC) {
#pragma unroll
        for (int t = 0; t < NPB * KC / 256; t++) {
            const int idx = t * 256 + tid;
            const int ln = idx / KC;
            const int k  = idx % KC;
            const int node = node0 + ln;
            Xs[k * XSTR + ln] = (node < n) ? X[(size_t)node * FIN + ck + k] : 0.f;
        }
#pragma unroll
        for (int t = 0; t < KC * FOUT / 256; t++) {
            const int idx = t * 256 + tid;
            Ws[idx] = W[(size_t)(ck + idx / FOUT) * FOUT + (idx % FOUT)];
        }
        __syncthreads();

#pragma unroll
        for (int k = 0; k < KC; k++) {
            const float4 wv = *(const float4*)&Ws[k * FOUT + tx * 4];
#pragma unroll
            for (int j = 0; j < 4; j++) {
                const float xv = Xs[k * XSTR + ty * 4 + j];
                acc[j][0] += xv * wv.x;
                acc[j][1] += xv * wv.y;
                acc[j][2] += xv * wv.z;
                acc[j][3] += xv * wv.w;
            }
        }
        __syncthreads();
    }

    float4 bv = make_float4(0.f, 0.f, 0.f, 0.f);
    if (BIAS) bv = *(const float4*)&b[tx * 4];

#pragma unroll
    for (int j = 0; j < 4; j++) {
        const int node = node0 + ty * 4 + j;
        if (node >= n) continue;
        float o0 = acc[j][0] + bv.x;
        float o1 = acc[j][1] + bv.y;
        float o2 = acc[j][2] + bv.z;
        float o3 = acc[j][3] + bv.w;
        if (ELU) {
            o0 = (o0 > 0.f) ? o0 : expm1f(o0);
            o1 = (o1 > 0.f) ? o1 : expm1f(o1);
            o2 = (o2 > 0.f) ? o2 : expm1f(o2);
            o3 = (o3 > 0.f) ? o3 : expm1f(o3);
        }
        if (WF) {
            float4 ov; ov.x = o0; ov.y = o1; ov.z = o2; ov.w = o3;
            *(float4*)(Yf + (size_t)node * FOUT + tx * 4) = ov;
        }
        if (WH) {
            __half2* hp = (__half2*)(Yh + (size_t)node * FOUT + tx * 4);
            hp[0] = __floats2half2_rn(o0, o1);
            hp[1] = __floats2half2_rn(o2, o3);
        }
    }
}

// ---------------- fused CSR aggregate ---------------------------------------
// out[i] = dinv[i]*sum_{e in seg(i)} gh[src(e)]*w(e) + gh[i]*dinv[i]^2 (+b,elu)
// F/8 lanes per node; each lane owns 8 halfs (one 16B load per edge).
template <int F, bool BE, bool WF, bool WH>
__global__ void k_agg(const __half* __restrict__ gh, const float* __restrict__ b,
                      float* __restrict__ outf, __half* __restrict__ outh, int n) {
    constexpr int LPE = F / 8;
    const long long tid = (long long)blockIdx.x * blockDim.x + threadIdx.x;
    const int node = (int)(tid / LPE);
    const int s = (int)(tid % LPE);
    if (node >= n) return;

    const __half* __restrict__ tbl = gh + s * 8;
    const int base = g_off[node];
    const int deg  = g_cnt[node];

    float a0 = 0.f, a1 = 0.f, a2 = 0.f, a3 = 0.f;
    float a4 = 0.f, a5 = 0.f, a6 = 0.f, a7 = 0.f;
    int k = 0;
#define GATH(ED)                                                               \
    {                                                                          \
        const float w_ = __uint_as_float((ED).y);                              \
        const uint4 raw_ = *(const uint4*)(tbl + (size_t)(ED).x * F);          \
        const float2 p0_ = __half22float2(*(const __half2*)&raw_.x);           \
        const float2 p1_ = __half22float2(*(const __half2*)&raw_.y);           \
        const float2 p2_ = __half22float2(*(const __half2*)&raw_.z);           \
        const float2 p3_ = __half22float2(*(const __half2*)&raw_.w);           \
        a0 += p0_.x * w_; a1 += p0_.y * w_;                                    \
        a2 += p1_.x * w_; a3 += p1_.y * w_;                                    \
        a4 += p2_.x * w_; a5 += p2_.y * w_;                                    \
        a6 += p3_.x * w_; a7 += p3_.y * w_;                                    \
    }
    for (; k + 4 <= deg; k += 4) {
        const uint2 e0 = g_edge[base + k],     e1 = g_edge[base + k + 1];
        const uint2 e2 = g_edge[base + k + 2], e3 = g_edge[base + k + 3];
        GATH(e0) GATH(e1) GATH(e2) GATH(e3)
    }
    for (; k < deg; k++) {
        const uint2 e0 = g_edge[base + k];
        GATH(e0)
    }
#undef GATH

    // scale by dinv[dst]; self-loop term h[node]*dinv^2
    const float dn = g_dinv[node];
    {
        const uint4 raw = *(const uint4*)(tbl + (size_t)node * F);
        const float2 p0 = __half22float2(*(const __half2*)&raw.x);
        const float2 p1 = __half22float2(*(const __half2*)&raw.y);
        const float2 p2 = __half22float2(*(const __half2*)&raw.z);
        const float2 p3 = __half22float2(*(const __half2*)&raw.w);
        a0 = (a0 + p0.x * dn) * dn; a1 = (a1 + p0.y * dn) * dn;
        a2 = (a2 + p1.x * dn) * dn; a3 = (a3 + p1.y * dn) * dn;
        a4 = (a4 + p2.x * dn) * dn; a5 = (a5 + p2.y * dn) * dn;
        a6 = (a6 + p3.x * dn) * dn; a7 = (a7 + p3.y * dn) * dn;
    }
    if (BE) {
        a0 += b[s * 8 + 0]; a1 += b[s * 8 + 1];
        a2 += b[s * 8 + 2]; a3 += b[s * 8 + 3];
        a4 += b[s * 8 + 4]; a5 += b[s * 8 + 5];
        a6 += b[s * 8 + 6]; a7 += b[s * 8 + 7];
        a0 = (a0 > 0.f) ? a0 : expm1f(a0);
        a1 = (a1 > 0.f) ? a1 : expm1f(a1);
        a2 = (a2 > 0.f) ? a2 : expm1f(a2);
        a3 = (a3 > 0.f) ? a3 : expm1f(a3);
        a4 = (a4 > 0.f) ? a4 : expm1f(a4);
        a5 = (a5 > 0.f) ? a5 : expm1f(a5);
        a6 = (a6 > 0.f) ? a6 : expm1f(a6);
        a7 = (a7 > 0.f) ? a7 : expm1f(a7);
    }
    if (WF) {
        float4 o0; o0.x = a0; o0.y = a1; o0.z = a2; o0.w = a3;
        float4 o1; o1.x = a4; o1.y = a5; o1.z = a6; o1.w = a7;
        float4* fp = (float4*)(outf + (size_t)node * F + s * 8);
        fp[0] = o0; fp[1] = o1;
    }
    if (WH) {
        __half2* hp = (__half2*)(outh + (size_t)node * F + s * 8);
        hp[0] = __floats2half2_rn(a0, a1);
        hp[1] = __floats2half2_rn(a2, a3);
        hp[2] = __floats2half2_rn(a4, a5);
        hp[3] = __floats2half2_rn(a6, a7);
    }
}

// ---------------- launch ---------------------------------------------------
static inline int cdiv(long long a, int b) { return (int)((a + b - 1) / b); }

// Lazy-created side stream + events (host resources only; no device memory).
static cudaStream_t s_side = nullptr;
static cudaEvent_t  s_evFork = nullptr, s_evJoin = nullptr;

extern "C" void kernel_launch(void* const* d_in, const int* in_sizes, int n_in,
                              void* d_out, int out_size) {
    const float* x  = (const float*)d_in[0];
    const int*   ei = (const int*)d_in[1];
    const float* ea = (const float*)d_in[2];
    const float* W1 = (const float*)d_in[3];
    const float* b1 = (const float*)d_in[4];
    const float* W2 = (const float*)d_in[5];
    const float* b2 = (const float*)d_in[6];
    const float* W3 = (const float*)d_in[7];
    const float* b3 = (const float*)d_in[8];
    float* out = (float*)d_out;

    const int n = in_sizes[0] / 128;   // 100000
    const int E = in_sizes[2];         // 3200000

    if (s_side == nullptr) {
        cudaStreamCreateWithFlags(&s_side, cudaStreamNonBlocking);
        cudaEventCreateWithFlags(&s_evFork, cudaEventDisableTiming);
        cudaEventCreateWithFlags(&s_evJoin, cudaEventDisableTiming);
    }

    void *p_t1h, *p_h1h, *p_s2, *p_h2h, *p_s3;
    cudaGetSymbolAddress(&p_t1h, g_t1h);
    cudaGetSymbolAddress(&p_h1h, g_h1h);
    cudaGetSymbolAddress(&p_s2,  g_s2);
    cudaGetSymbolAddress(&p_h2h, g_h2h);
    cudaGetSymbolAddress(&p_s3,  g_s3);

    const int T = 256;

    // --- fork: GEMM1 (x@W1, independent of CSR prep) on side stream ---
    cudaEventRecord(s_evFork, 0);
    cudaStreamWaitEvent(s_side, s_evFork, 0);
    k_gemm<128, 32, false, false, false, true><<<cdiv(n, 128), 256, 0, s_side>>>(
        x, W1, nullptr, nullptr, (__half*)p_t1h, n);
    cudaEventRecord(s_evJoin, s_side);

    // --- prep: degrees+dinv, counter-based offsets, CSR fill (main) ---
    k_init<<<cdiv(n, T), T>>>(ei, n);
    k_prep<<<cdiv(E, T), T>>>(ei, ea, E, n);
    k_assign<<<cdiv(n, T), T>>>(n);
    k_fill<<<cdiv(E, T), T>>>(ei, ea, E, n);

    // --- join: layer-1 agg needs both t1h (side) and CSR (main) ---
    cudaStreamWaitEvent(0, s_evJoin, 0);
    k_agg<32, true, false, true><<<cdiv((long long)n * 4, T), T>>>(
        (const __half*)p_t1h, b1, nullptr, (__half*)p_h1h, n);

    // --- layer 2: s2 = A h1 ; h2 = elu(s2@W2 + b2) ---
    k_agg<32, false, true, false><<<cdiv((long long)n * 4, T), T>>>(
        (const __half*)p_h1h, nullptr, (float*)p_s2, nullptr, n);
    k_gemm<32, 64, true, true, false, true><<<cdiv(n, 64), 256>>>(
        (const float*)p_s2, W2, b2, nullptr, (__half*)p_h2h, n);

    // --- layer 3: s3 = A h2 ; out = s3@W3 + b3 ---
    k_agg<64, false, true, false><<<cdiv((long long)n * 8, T), T>>>(
        (const __half*)p_h2h, nullptr, (float*)p_s3, nullptr, n);
    k_gemm<64, 128, true, false, true, false><<<cdiv(n, 32), 256>>>(
        (const float*)p_s3, W3, b3, out, nullptr, n);
}

// round 14
// speedup vs baseline: 1.1578x; 1.0084x over previous
#include <cuda_runtime.h>
#include <cuda_fp16.h>
#include <cstdint>

#define NN 100000
#define NE 3200000
#define DEG_SCALE 33554432.0f   // 2^25 fixed-point for packed degree

// ---------------- scratch (device globals; no allocation allowed) ----------
__device__ __align__(16) unsigned long long g_pack[NN]; // {cnt<<40 | deg*2^25}
__device__ __align__(16) float g_dinv[NN];
__device__ __align__(16) int   g_cnt[NN];
__device__ __align__(16) int   g_off[NN];
__device__ __align__(16) int   g_cur[NN];
__device__ int g_total;
__device__ int g_is64;

__device__ __align__(16) uint2 g_edge[NE];      // CSR: {src, fp32 w=dinv[src]*ea}

__device__ __align__(16) __half g_t1h[NN * 32]; // x @ W1 (fp16)
__device__ __align__(16) __half g_h1h[NN * 32]; // elu layer-1 out (fp16)
__device__ __align__(16) float  g_s2 [NN * 32]; // A @ h1 (fp32)
__device__ __align__(16) __half g_h2h[NN * 64]; // elu layer-2 out (fp16)
__device__ __align__(16) float  g_s3 [NN * 64]; // A @ h2 (fp32)

// ---------------- packed f32x2 helpers --------------------------------------
__device__ __forceinline__ unsigned long long pack_f32x2(float lo, float hi) {
    unsigned long long r;
    asm("mov.b64 %0, {%1, %2};" : "=l"(r) : "f"(lo), "f"(hi));
    return r;
}
__device__ __forceinline__ void unpack_f32x2(unsigned long long v,
                                             float& lo, float& hi) {
    asm("mov.b64 {%0, %1}, %2;" : "=f"(lo), "=f"(hi) : "l"(v));
}
__device__ __forceinline__ void fma_f32x2(unsigned long long& d,
                                          unsigned long long a,
                                          unsigned long long b) {
    asm("fma.rn.f32x2 %0, %1, %2, %0;" : "+l"(d) : "l"(a), "l"(b));
}

// ---------------- init + dtype detect (merged) -----------------------------
__global__ void k_init(const int* __restrict__ ei32, int n) {
    if (blockIdx.x == 0) {
        __shared__ int cnt;
        if (threadIdx.x == 0) { cnt = 0; g_total = 0; }
        __syncthreads();
        int zeros = 0;
        for (int i = threadIdx.x; i < 1024; i += blockDim.x)
            if (ei32[2 * i + 1] == 0) zeros++;
        atomicAdd(&cnt, zeros);
        __syncthreads();
        if (threadIdx.x == 0) g_is64 = (cnt > 900) ? 1 : 0;
    }
    int i = blockIdx.x * blockDim.x + threadIdx.x;
    if (i < n) g_pack[i] = (unsigned long long)DEG_SCALE;  // deg=1 (self), cnt=0
}

__device__ __forceinline__ void load_edge(const int* __restrict__ ei32,
                                          int e, int E, int n, int& r, int& c) {
    if (g_is64) {
        r = ei32[2 * (long long)e];
        c = ei32[2 * ((long long)E + e)];
    } else {
        r = ei32[e];
        c = ei32[E + e];
    }
    if ((unsigned)r >= (unsigned)n) r = 0;
    if ((unsigned)c >= (unsigned)n) c = 0;
}

__global__ void k_prep(const int* __restrict__ ei32,
                       const float* __restrict__ ea, int E, int n) {
    int e = blockIdx.x * blockDim.x + threadIdx.x;
    if (e >= E) return;
    int c;
    if (g_is64) c = ei32[2 * ((long long)E + e)];
    else        c = ei32[E + e];
    if ((unsigned)c >= (unsigned)n) c = 0;
    const unsigned long long add =
        (1ULL << 40) | (unsigned long long)(fmaxf(ea[e], 0.f) * DEG_SCALE + 0.5f);
    atomicAdd(&g_pack[c], add);
}

// ---------------- assign: dinv decode + counter-based segment reservation ---
__global__ void k_assign(int n) {
    int i = blockIdx.x * blockDim.x + threadIdx.x;
    if (i >= n) return;
    const unsigned long long p = g_pack[i];
    const int cnt = (int)(p >> 40);
    g_cnt[i] = cnt;
    const float d = (float)(p & 0xFFFFFFFFFFULL) * (1.0f / DEG_SCALE);
    g_dinv[i] = (d > 0.0f) ? rsqrtf(fmaxf(d, 1e-30f)) : 0.0f;
    const int pos = atomicAdd(&g_total, cnt);
    g_off[i] = pos;
    g_cur[i] = pos;
}

// ---------------- CSR fill: w = dinv[src]*ea (dst factor applied in agg) ---
__global__ void k_fill(const int* __restrict__ ei32,
                       const float* __restrict__ ea, int E, int n) {
    int e = blockIdx.x * blockDim.x + threadIdx.x;
    if (e >= E) return;
    int r, c;
    load_edge(ei32, e, E, n, r, c);
    const int pos = atomicAdd(&g_cur[c], 1);
    const float w = g_dinv[r] * ea[e];
    g_edge[pos] = make_uint2((unsigned)r, __float_as_uint(w));
}

// ---------------- register-tiled GEMM (f32x2 dual-FMA) with fused epilogue --
// 256 threads; thread tile = 4 nodes x 4 fouts; X staged transposed in smem.
// Inner loop: weight float4 reinterpreted as 2 packed f32x2 operands;
// 8 fma.rn.f32x2 replace 16 FFMA per k-step (identical fp32 rounding).
template <int FIN, int FOUT, bool BIAS, bool ELU, bool WF, bool WH>
__global__ void k_gemm(const float* __restrict__ X, const float* __restrict__ W,
                       const float* __restrict__ b, float* __restrict__ Yf,
                       __half* __restrict__ Yh, int n) {
    constexpr int BX   = FOUT / 4;
    constexpr int BY   = 256 / BX;
    constexpr int NPB  = BY * 4;
    constexpr int KC   = 32;
    constexpr int XSTR = NPB + 1;

    __shared__ float Xs[KC * XSTR];
    __shared__ float Ws[KC * FOUT];

    const int tid = threadIdx.x;
    const int tx = tid % BX;
    const int ty = tid / BX;
    const int node0 = blockIdx.x * NPB;

    unsigned long long acc01[4] = {0ULL, 0ULL, 0ULL, 0ULL};
    unsigned long long acc23[4] = {0ULL, 0ULL, 0ULL, 0ULL};

    for (int ck = 0; ck < FIN; ck += KC) {
#pragma unroll
        for (int t = 0; t < NPB * KC / 256; t++) {
            const int idx = t * 256 + tid;
            const int ln = idx / KC;
            const int k  = idx % KC;
            const int node = node0 + ln;
            Xs[k * XSTR + ln] = (node < n) ? X[(size_t)node * FIN + ck + k] : 0.f;
        }
#pragma unroll
        for (int t = 0; t < KC * FOUT / 256; t++) {
            const int idx = t * 256 + tid;
            Ws[idx] = W[(size_t)(ck + idx / FOUT) * FOUT + (idx % FOUT)];
        }
        __syncthreads();

#pragma unroll
        for (int k = 0; k < KC; k++) {
            const ulonglong2 wp = *(const ulonglong2*)&Ws[k * FOUT + tx * 4];
#pragma unroll
            for (int j = 0; j < 4; j++) {
                const float xv = Xs[k * XSTR + ty * 4 + j];
                const unsigned long long xx = pack_f32x2(xv, xv);
                fma_f32x2(acc01[j], xx, wp.x);
                fma_f32x2(acc23[j], xx, wp.y);
            }
        }
        __syncthreads();
    }

    float4 bv = make_float4(0.f, 0.f, 0.f, 0.f);
    if (BIAS) bv = *(const float4*)&b[tx * 4];

#pragma unroll
    for (int j = 0; j < 4; j++) {
        const int node = node0 + ty * 4 + j;
        if (node >= n) continue;
        float o0, o1, o2, o3;
        unpack_f32x2(acc01[j], o0, o1);
        unpack_f32x2(acc23[j], o2, o3);
        o0 += bv.x; o1 += bv.y; o2 += bv.z; o3 += bv.w;
        if (ELU) {
            o0 = (o0 > 0.f) ? o0 : expm1f(o0);
            o1 = (o1 > 0.f) ? o1 : expm1f(o1);
            o2 = (o2 > 0.f) ? o2 : expm1f(o2);
            o3 = (o3 > 0.f) ? o3 : expm1f(o3);
        }
        if (WF) {
            float4 ov; ov.x = o0; ov.y = o1; ov.z = o2; ov.w = o3;
            *(float4*)(Yf + (size_t)node * FOUT + tx * 4) = ov;
        }
        if (WH) {
            __half2* hp = (__half2*)(Yh + (size_t)node * FOUT + tx * 4);
            hp[0] = __floats2half2_rn(o0, o1);
            hp[1] = __floats2half2_rn(o2, o3);
        }
    }
}

// ---------------- fused CSR aggregate ---------------------------------------
// out[i] = dinv[i]*sum_{e in seg(i)} gh[src(e)]*w(e) + gh[i]*dinv[i]^2 (+b,elu)
// F/8 lanes per node; each lane owns 8 halfs (one 16B load per edge).
template <int F, bool BE, bool WF, bool WH>
__global__ void k_agg(const __half* __restrict__ gh, const float* __restrict__ b,
                      float* __restrict__ outf, __half* __restrict__ outh, int n) {
    constexpr int LPE = F / 8;
    const long long tid = (long long)blockIdx.x * blockDim.x + threadIdx.x;
    const int node = (int)(tid / LPE);
    const int s = (int)(tid % LPE);
    if (node >= n) return;

    const __half* __restrict__ tbl = gh + s * 8;
    const int base = g_off[node];
    const int deg  = g_cnt[node];

    float a0 = 0.f, a1 = 0.f, a2 = 0.f, a3 = 0.f;
    float a4 = 0.f, a5 = 0.f, a6 = 0.f, a7 = 0.f;
    int k = 0;
#define GATH(ED)                                                               \
    {                                                                          \
        const float w_ = __uint_as_float((ED).y);                              \
        const uint4 raw_ = *(const uint4*)(tbl + (size_t)(ED).x * F);          \
        const float2 p0_ = __half22float2(*(const __half2*)&raw_.x);           \
        const float2 p1_ = __half22float2(*(const __half2*)&raw_.y);           \
        const float2 p2_ = __half22float2(*(const __half2*)&raw_.z);           \
        const float2 p3_ = __half22float2(*(const __half2*)&raw_.w);           \
        a0 += p0_.x * w_; a1 += p0_.y * w_;                                    \
        a2 += p1_.x * w_; a3 += p1_.y * w_;                                    \
        a4 += p2_.x * w_; a5 += p2_.y * w_;                                    \
        a6 += p3_.x * w_; a7 += p3_.y * w_;                                    \
    }
    for (; k + 4 <= deg; k += 4) {
        const uint2 e0 = g_edge[base + k],     e1 = g_edge[base + k + 1];
        const uint2 e2 = g_edge[base + k + 2], e3 = g_edge[base + k + 3];
        GATH(e0) GATH(e1) GATH(e2) GATH(e3)
    }
    for (; k < deg; k++) {
        const uint2 e0 = g_edge[base + k];
        GATH(e0)
    }
#undef GATH

    // scale by dinv[dst]; self-loop term h[node]*dinv^2
    const float dn = g_dinv[node];
    {
        const uint4 raw = *(const uint4*)(tbl + (size_t)node * F);
        const float2 p0 = __half22float2(*(const __half2*)&raw.x);
        const float2 p1 = __half22float2(*(const __half2*)&raw.y);
        const float2 p2 = __half22float2(*(const __half2*)&raw.z);
        const float2 p3 = __half22float2(*(const __half2*)&raw.w);
        a0 = (a0 + p0.x * dn) * dn; a1 = (a1 + p0.y * dn) * dn;
        a2 = (a2 + p1.x * dn) * dn; a3 = (a3 + p1.y * dn) * dn;
        a4 = (a4 + p2.x * dn) * dn; a5 = (a5 + p2.y * dn) * dn;
        a6 = (a6 + p3.x * dn) * dn; a7 = (a7 + p3.y * dn) * dn;
    }
    if (BE) {
        a0 += b[s * 8 + 0]; a1 += b[s * 8 + 1];
        a2 += b[s * 8 + 2]; a3 += b[s * 8 + 3];
        a4 += b[s * 8 + 4]; a5 += b[s * 8 + 5];
        a6 += b[s * 8 + 6]; a7 += b[s * 8 + 7];
        a0 = (a0 > 0.f) ? a0 : expm1f(a0);
        a1 = (a1 > 0.f) ? a1 : expm1f(a1);
        a2 = (a2 > 0.f) ? a2 : expm1f(a2);
        a3 = (a3 > 0.f) ? a3 : expm1f(a3);
        a4 = (a4 > 0.f) ? a4 : expm1f(a4);
        a5 = (a5 > 0.f) ? a5 : expm1f(a5);
        a6 = (a6 > 0.f) ? a6 : expm1f(a6);
        a7 = (a7 > 0.f) ? a7 : expm1f(a7);
    }
    if (WF) {
        float4 o0; o0.x = a0; o0.y = a1; o0.z = a2; o0.w = a3;
        float4 o1; o1.x = a4; o1.y = a5; o1.z = a6; o1.w = a7;
        float4* fp = (float4*)(outf + (size_t)node * F + s * 8);
        fp[0] = o0; fp[1] = o1;
    }
    if (WH) {
        __half2* hp = (__half2*)(outh + (size_t)node * F + s * 8);
        hp[0] = __floats2half2_rn(a0, a1);
        hp[1] = __floats2half2_rn(a2, a3);
        hp[2] = __floats2half2_rn(a4, a5);
        hp[3] = __floats2half2_rn(a6, a7);
    }
}

// ---------------- launch ---------------------------------------------------
static inline int cdiv(long long a, int b) { return (int)((a + b - 1) / b); }

// Lazy-created side stream + events (host resources only; no device memory).
static cudaStream_t s_side = nullptr;
static cudaEvent_t  s_evFork = nullptr, s_evJoin = nullptr;

extern "C" void kernel_launch(void* const* d_in, const int* in_sizes, int n_in,
                              void* d_out, int out_size) {
    const float* x  = (const float*)d_in[0];
    const int*   ei = (const int*)d_in[1];
    const float* ea = (const float*)d_in[2];
    const float* W1 = (const float*)d_in[3];
    const float* b1 = (const float*)d_in[4];
    const float* W2 = (const float*)d_in[5];
    const float* b2 = (const float*)d_in[6];
    const float* W3 = (const float*)d_in[7];
    const float* b3 = (const float*)d_in[8];
    float* out = (float*)d_out;

    const int n = in_sizes[0] / 128;   // 100000
    const int E = in_sizes[2];         // 3200000

    if (s_side == nullptr) {
        cudaStreamCreateWithFlags(&s_side, cudaStreamNonBlocking);
        cudaEventCreateWithFlags(&s_evFork, cudaEventDisableTiming);
        cudaEventCreateWithFlags(&s_evJoin, cudaEventDisableTiming);
    }

    void *p_t1h, *p_h1h, *p_s2, *p_h2h, *p_s3;
    cudaGetSymbolAddress(&p_t1h, g_t1h);
    cudaGetSymbolAddress(&p_h1h, g_h1h);
    cudaGetSymbolAddress(&p_s2,  g_s2);
    cudaGetSymbolAddress(&p_h2h, g_h2h);
    cudaGetSymbolAddress(&p_s3,  g_s3);

    const int T = 256;

    // --- fork: GEMM1 (x@W1, independent of CSR prep) on side stream ---
    cudaEventRecord(s_evFork, 0);
    cudaStreamWaitEvent(s_side, s_evFork, 0);
    k_gemm<128, 32, false, false, false, true><<<cdiv(n, 128), 256, 0, s_side>>>(
        x, W1, nullptr, nullptr, (__half*)p_t1h, n);
    cudaEventRecord(s_evJoin, s_side);

    // --- prep: degrees+dinv, counter-based offsets, CSR fill (main) ---
    k_init<<<cdiv(n, T), T>>>(ei, n);
    k_prep<<<cdiv(E, T), T>>>(ei, ea, E, n);
    k_assign<<<cdiv(n, T), T>>>(n);
    k_fill<<<cdiv(E, T), T>>>(ei, ea, E, n);

    // --- join: layer-1 agg needs both t1h (side) and CSR (main) ---
    cudaStreamWaitEvent(0, s_evJoin, 0);
    k_agg<32, true, false, true><<<cdiv((long long)n * 4, T), T>>>(
        (const __half*)p_t1h, b1, nullptr, (__half*)p_h1h, n);

    // --- layer 2: s2 = A h1 ; h2 = elu(s2@W2 + b2) ---
    k_agg<32, false, true, false><<<cdiv((long long)n * 4, T), T>>>(
        (const __half*)p_h1h, nullptr, (float*)p_s2, nullptr, n);
    k_gemm<32, 64, true, true, false, true><<<cdiv(n, 64), 256>>>(
        (const float*)p_s2, W2, b2, nullptr, (__half*)p_h2h, n);

    // --- layer 3: s3 = A h2 ; out = s3@W3 + b3 ---
    k_agg<64, false, true, false><<<cdiv((long long)n * 8, T), T>>>(
        (const __half*)p_h2h, nullptr, (float*)p_s3, nullptr, n);
    k_gemm<64, 128, true, false, true, false><<<cdiv(n, 32), 256>>>(
        (const float*)p_s3, W3, b3, out, nullptr, n);
}

// round 15
// speedup vs baseline: 1.1658x; 1.0069x over previous
#include <cuda_runtime.h>
#include <cuda_fp16.h>
#include <cstdint>

#define NN 100000
#define NE 3200000
#define DEG_SCALE 33554432.0f   // 2^25 fixed-point for packed degree

// ---------------- scratch (device globals; no allocation allowed) ----------
// g_pack invariant: ZERO before each kernel_launch execution. Zero-initialized
// at load; k_assign resets each slot after consuming it. Self-loop (deg=1) is
// baked into the decode in k_assign instead of an init pass.
__device__ unsigned long long g_pack[NN];       // {cnt<<40 | sum(ea)*2^25}
__device__ __align__(16) float g_dinv[NN];
__device__ __align__(16) int   g_cnt[NN];
__device__ __align__(16) int   g_off[NN];
__device__ __align__(16) int   g_cur[NN];
__device__ int g_total;
__device__ int g_is64;

__device__ __align__(16) uint2 g_edge[NE];      // CSR: {src, fp32 w=dinv[src]*ea}

__device__ __align__(16) __half g_t1h[NN * 32]; // x @ W1 (fp16)
__device__ __align__(16) __half g_h1h[NN * 32]; // elu layer-1 out (fp16)
__device__ __align__(16) __half g_s2h[NN * 32]; // A @ h1 (fp16)
__device__ __align__(16) __half g_h2h[NN * 64]; // elu layer-2 out (fp16)
__device__ __align__(16) __half g_s3h[NN * 64]; // A @ h2 (fp16)

// ---------------- packed f32x2 helpers --------------------------------------
__device__ __forceinline__ unsigned long long pack_f32x2(float lo, float hi) {
    unsigned long long r;
    asm("mov.b64 %0, {%1, %2};" : "=l"(r) : "f"(lo), "f"(hi));
    return r;
}
__device__ __forceinline__ void unpack_f32x2(unsigned long long v,
                                             float& lo, float& hi) {
    asm("mov.b64 {%0, %1}, %2;" : "=f"(lo), "=f"(hi) : "l"(v));
}
__device__ __forceinline__ void fma_f32x2(unsigned long long& d,
                                          unsigned long long a,
                                          unsigned long long b) {
    asm("fma.rn.f32x2 %0, %1, %2, %0;" : "+l"(d) : "l"(a), "l"(b));
}

// ---------------- dtype detect (1 block) ------------------------------------
__global__ void k_detect(const int* __restrict__ ei32) {
    __shared__ int cnt;
    if (threadIdx.x == 0) { cnt = 0; g_total = 0; }
    __syncthreads();
    int zeros = 0;
    for (int i = threadIdx.x; i < 1024; i += blockDim.x)
        if (ei32[2 * i + 1] == 0) zeros++;
    atomicAdd(&cnt, zeros);
    __syncthreads();
    if (threadIdx.x == 0) g_is64 = (cnt > 900) ? 1 : 0;
}

__device__ __forceinline__ void load_edge(const int* __restrict__ ei32,
                                          int e, int E, int n, int& r, int& c) {
    if (g_is64) {
        r = ei32[2 * (long long)e];
        c = ei32[2 * ((long long)E + e)];
    } else {
        r = ei32[e];
        c = ei32[E + e];
    }
    if ((unsigned)r >= (unsigned)n) r = 0;
    if ((unsigned)c >= (unsigned)n) c = 0;
}

__global__ void k_prep(const int* __restrict__ ei32,
                       const float* __restrict__ ea, int E, int n) {
    int e = blockIdx.x * blockDim.x + threadIdx.x;
    if (e >= E) return;
    int c;
    if (g_is64) c = ei32[2 * ((long long)E + e)];
    else        c = ei32[E + e];
    if ((unsigned)c >= (unsigned)n) c = 0;
    const unsigned long long add =
        (1ULL << 40) | (unsigned long long)(fmaxf(ea[e], 0.f) * DEG_SCALE + 0.5f);
    atomicAdd(&g_pack[c], add);
}

// ---------------- assign: dinv decode + counter-based segment reservation ---
// Self-loop weight 1 folded into decode; resets g_pack for the next launch.
__global__ void k_assign(int n) {
    int i = blockIdx.x * blockDim.x + threadIdx.x;
    if (i >= n) return;
    const unsigned long long p = g_pack[i];
    g_pack[i] = 0ULL;                              // restore invariant
    const int cnt = (int)(p >> 40);
    g_cnt[i] = cnt;
    const float d = 1.0f + (float)(p & 0xFFFFFFFFFFULL) * (1.0f / DEG_SCALE);
    g_dinv[i] = rsqrtf(d);
    const int pos = atomicAdd(&g_total, cnt);
    g_off[i] = pos;
    g_cur[i] = pos;
}

// ---------------- CSR fill: w = dinv[src]*ea (dst factor applied in agg) ---
__global__ void k_fill(const int* __restrict__ ei32,
                       const float* __restrict__ ea, int E, int n) {
    int e = blockIdx.x * blockDim.x + threadIdx.x;
    if (e >= E) return;
    int r, c;
    load_edge(ei32, e, E, n, r, c);
    const int pos = atomicAdd(&g_cur[c], 1);
    const float w = g_dinv[r] * ea[e];
    g_edge[pos] = make_uint2((unsigned)r, __float_as_uint(w));
}

// ---------------- register-tiled GEMM (f32x2 dual-FMA) with fused epilogue --
__device__ __forceinline__ float to_f32(float v) { return v; }
__device__ __forceinline__ float to_f32(__half v) { return __half2float(v); }

template <int FIN, int FOUT, bool BIAS, bool ELU, bool WF, bool WH, typename IT>
__global__ void k_gemm(const IT* __restrict__ X, const float* __restrict__ W,
                       const float* __restrict__ b, float* __restrict__ Yf,
                       __half* __restrict__ Yh, int n) {
    constexpr int BX   = FOUT / 4;
    constexpr int BY   = 256 / BX;
    constexpr int NPB  = BY * 4;
    constexpr int KC   = 32;
    constexpr int XSTR = NPB + 1;

    __shared__ float Xs[KC * XSTR];
    __shared__ float Ws[KC * FOUT];

    const int tid = threadIdx.x;
    const int tx = tid % BX;
    const int ty = tid / BX;
    const int node0 = blockIdx.x * NPB;

    unsigned long long acc01[4] = {0ULL, 0ULL, 0ULL, 0ULL};
    unsigned long long acc23[4] = {0ULL, 0ULL, 0ULL, 0ULL};

    for (int ck = 0; ck < FIN; ck += KC) {
#pragma unroll
        for (int t = 0; t < NPB * KC / 256; t++) {
            const int idx = t * 256 + tid;
            const int ln = idx / KC;
            const int k  = idx % KC;
            const int node = node0 + ln;
            Xs[k * XSTR + ln] =
                (node < n) ? to_f32(X[(size_t)node * FIN + ck + k]) : 0.f;
        }
#pragma unroll
        for (int t = 0; t < KC * FOUT / 256; t++) {
            const int idx = t * 256 + tid;
            Ws[idx] = W[(size_t)(ck + idx / FOUT) * FOUT + (idx % FOUT)];
        }
        __syncthreads();

#pragma unroll
        for (int k = 0; k < KC; k++) {
            const ulonglong2 wp = *(const ulonglong2*)&Ws[k * FOUT + tx * 4];
#pragma unroll
            for (int j = 0; j < 4; j++) {
                const float xv = Xs[k * XSTR + ty * 4 + j];
                const unsigned long long xx = pack_f32x2(xv, xv);
                fma_f32x2(acc01[j], xx, wp.x);
                fma_f32x2(acc23[j], xx, wp.y);
            }
        }
        __syncthreads();
    }

    float4 bv = make_float4(0.f, 0.f, 0.f, 0.f);
    if (BIAS) bv = *(const float4*)&b[tx * 4];

#pragma unroll
    for (int j = 0; j < 4; j++) {
        const int node = node0 + ty * 4 + j;
        if (node >= n) continue;
        float o0, o1, o2, o3;
        unpack_f32x2(acc01[j], o0, o1);
        unpack_f32x2(acc23[j], o2, o3);
        o0 += bv.x; o1 += bv.y; o2 += bv.z; o3 += bv.w;
        if (ELU) {
            o0 = (o0 > 0.f) ? o0 : expm1f(o0);
            o1 = (o1 > 0.f) ? o1 : expm1f(o1);
            o2 = (o2 > 0.f) ? o2 : expm1f(o2);
            o3 = (o3 > 0.f) ? o3 : expm1f(o3);
        }
        if (WF) {
            float4 ov; ov.x = o0; ov.y = o1; ov.z = o2; ov.w = o3;
            *(float4*)(Yf + (size_t)node * FOUT + tx * 4) = ov;
        }
        if (WH) {
            __half2* hp = (__half2*)(Yh + (size_t)node * FOUT + tx * 4);
            hp[0] = __floats2half2_rn(o0, o1);
            hp[1] = __floats2half2_rn(o2, o3);
        }
    }
}

// ---------------- fused CSR aggregate ---------------------------------------
// out[i] = dinv[i]*sum_{e in seg(i)} gh[src(e)]*w(e) + gh[i]*dinv[i]^2 (+b,elu)
// F/8 lanes per node; each lane owns 8 halfs (one 16B load per edge).
template <int F, bool BE>
__global__ void k_agg(const __half* __restrict__ gh, const float* __restrict__ b,
                      __half* __restrict__ outh, int n) {
    constexpr int LPE = F / 8;
    const long long tid = (long long)blockIdx.x * blockDim.x + threadIdx.x;
    const int node = (int)(tid / LPE);
    const int s = (int)(tid % LPE);
    if (node >= n) return;

    const __half* __restrict__ tbl = gh + s * 8;
    const int base = g_off[node];
    const int deg  = g_cnt[node];

    float a0 = 0.f, a1 = 0.f, a2 = 0.f, a3 = 0.f;
    float a4 = 0.f, a5 = 0.f, a6 = 0.f, a7 = 0.f;
    int k = 0;
#define GATH(ED)                                                               \
    {                                                                          \
        const float w_ = __uint_as_float((ED).y);                              \
        const uint4 raw_ = *(const uint4*)(tbl + (size_t)(ED).x * F);          \
        const float2 p0_ = __half22float2(*(const __half2*)&raw_.x);           \
        const float2 p1_ = __half22float2(*(const __half2*)&raw_.y);           \
        const float2 p2_ = __half22float2(*(const __half2*)&raw_.z);           \
        const float2 p3_ = __half22float2(*(const __half2*)&raw_.w);           \
        a0 += p0_.x * w_; a1 += p0_.y * w_;                                    \
        a2 += p1_.x * w_; a3 += p1_.y * w_;                                    \
        a4 += p2_.x * w_; a5 += p2_.y * w_;                                    \
        a6 += p3_.x * w_; a7 += p3_.y * w_;                                    \
    }
    for (; k + 4 <= deg; k += 4) {
        const uint2 e0 = g_edge[base + k],     e1 = g_edge[base + k + 1];
        const uint2 e2 = g_edge[base + k + 2], e3 = g_edge[base + k + 3];
        GATH(e0) GATH(e1) GATH(e2) GATH(e3)
    }
    for (; k < deg; k++) {
        const uint2 e0 = g_edge[base + k];
        GATH(e0)
    }
#undef GATH

    // scale by dinv[dst]; self-loop term h[node]*dinv^2
    const float dn = g_dinv[node];
    {
        const uint4 raw = *(const uint4*)(tbl + (size_t)node * F);
        const float2 p0 = __half22float2(*(const __half2*)&raw.x);
        const float2 p1 = __half22float2(*(const __half2*)&raw.y);
        const float2 p2 = __half22float2(*(const __half2*)&raw.z);
        const float2 p3 = __half22float2(*(const __half2*)&raw.w);
        a0 = (a0 + p0.x * dn) * dn; a1 = (a1 + p0.y * dn) * dn;
        a2 = (a2 + p1.x * dn) * dn; a3 = (a3 + p1.y * dn) * dn;
        a4 = (a4 + p2.x * dn) * dn; a5 = (a5 + p2.y * dn) * dn;
        a6 = (a6 + p3.x * dn) * dn; a7 = (a7 + p3.y * dn) * dn;
    }
    if (BE) {
        a0 += b[s * 8 + 0]; a1 += b[s * 8 + 1];
        a2 += b[s * 8 + 2]; a3 += b[s * 8 + 3];
        a4 += b[s * 8 + 4]; a5 += b[s * 8 + 5];
        a6 += b[s * 8 + 6]; a7 += b[s * 8 + 7];
        a0 = (a0 > 0.f) ? a0 : expm1f(a0);
        a1 = (a1 > 0.f) ? a1 : expm1f(a1);
        a2 = (a2 > 0.f) ? a2 : expm1f(a2);
        a3 = (a3 > 0.f) ? a3 : expm1f(a3);
        a4 = (a4 > 0.f) ? a4 : expm1f(a4);
        a5 = (a5 > 0.f) ? a5 : expm1f(a5);
        a6 = (a6 > 0.f) ? a6 : expm1f(a6);
        a7 = (a7 > 0.f) ? a7 : expm1f(a7);
    }
    __half2* hp = (__half2*)(outh + (size_t)node * F + s * 8);
    hp[0] = __floats2half2_rn(a0, a1);
    hp[1] = __floats2half2_rn(a2, a3);
    hp[2] = __floats2half2_rn(a4, a5);
    hp[3] = __floats2half2_rn(a6, a7);
}

// ---------------- launch ---------------------------------------------------
static inline int cdiv(long long a, int b) { return (int)((a + b - 1) / b); }

// Lazy-created side stream + events (host resources only; no device memory).
static cudaStream_t s_side = nullptr;
static cudaEvent_t  s_evFork = nullptr, s_evJoin = nullptr;

extern "C" void kernel_launch(void* const* d_in, const int* in_sizes, int n_in,
                              void* d_out, int out_size) {
    const float* x  = (const float*)d_in[0];
    const int*   ei = (const int*)d_in[1];
    const float* ea = (const float*)d_in[2];
    const float* W1 = (const float*)d_in[3];
    const float* b1 = (const float*)d_in[4];
    const float* W2 = (const float*)d_in[5];
    const float* b2 = (const float*)d_in[6];
    const float* W3 = (const float*)d_in[7];
    const float* b3 = (const float*)d_in[8];
    float* out = (float*)d_out;

    const int n = in_sizes[0] / 128;   // 100000
    const int E = in_sizes[2];         // 3200000

    if (s_side == nullptr) {
        cudaStreamCreateWithFlags(&s_side, cudaStreamNonBlocking);
        cudaEventCreateWithFlags(&s_evFork, cudaEventDisableTiming);
        cudaEventCreateWithFlags(&s_evJoin, cudaEventDisableTiming);
    }

    void *p_t1h, *p_h1h, *p_s2h, *p_h2h, *p_s3h;
    cudaGetSymbolAddress(&p_t1h, g_t1h);
    cudaGetSymbolAddress(&p_h1h, g_h1h);
    cudaGetSymbolAddress(&p_s2h, g_s2h);
    cudaGetSymbolAddress(&p_h2h, g_h2h);
    cudaGetSymbolAddress(&p_s3h, g_s3h);

    const int T = 256;

    // --- fork: GEMM1 (x@W1, independent of CSR prep) on side stream ---
    cudaEventRecord(s_evFork, 0);
    cudaStreamWaitEvent(s_side, s_evFork, 0);
    k_gemm<128, 32, false, false, false, true, float>
        <<<cdiv(n, 128), 256, 0, s_side>>>(
        x, W1, nullptr, nullptr, (__half*)p_t1h, n);
    cudaEventRecord(s_evJoin, s_side);

    // --- prep: detect, degree atomics, offsets, CSR fill (main stream) ---
    k_detect<<<1, 256>>>(ei);
    k_prep<<<cdiv(E, T), T>>>(ei, ea, E, n);
    k_assign<<<cdiv(n, T), T>>>(n);
    k_fill<<<cdiv(E, T), T>>>(ei, ea, E, n);

    // --- join: layer-1 agg needs both t1h (side) and CSR (main) ---
    cudaStreamWaitEvent(0, s_evJoin, 0);
    k_agg<32, true><<<cdiv((long long)n * 4, T), T>>>(
        (const __half*)p_t1h, b1, (__half*)p_h1h, n);

    // --- layer 2: s2 = A h1 (fp16) ; h2 = elu(s2@W2 + b2) (fp16) ---
    k_agg<32, false><<<cdiv((long long)n * 4, T), T>>>(
        (const __half*)p_h1h, nullptr, (__half*)p_s2h, n);
    k_gemm<32, 64, true, true, false, true, __half><<<cdiv(n, 64), 256>>>(
        (const __half*)p_s2h, W2, b2, nullptr, (__half*)p_h2h, n);

    // --- layer 3: s3 = A h2 (fp16) ; out = s3@W3 + b3 ---
    k_agg<64, false><<<cdiv((long long)n * 8, T), T>>>(
        (const __half*)p_h2h, nullptr, (__half*)p_s3h, n);
    k_gemm<64, 128, true, false, true, false, __half><<<cdiv(n, 32), 256>>>(
        (const __half*)p_s3h, W3, b3, out, nullptr, n);
}

// round 16
// speedup vs baseline: 1.2448x; 1.0678x over previous
#include <cuda_runtime.h>
#include <cuda_fp16.h>
#include <cstdint>

#define NN 100000
#define NE 3200000
#define DEG_SCALE 33554432.0f   // 2^25 fixed-point for packed degree

// ---------------- scratch (device globals; no allocation allowed) ----------
// g_pack invariant: ZERO before each kernel_launch execution. Zero-initialized
// at load; k_assign resets each slot after consuming it.
__device__ unsigned long long g_pack[NN];       // {cnt<<40 | sum(ea)*2^25}
__device__ __align__(16) float g_dinv[NN];
__device__ __align__(16) int   g_cnt[NN];
__device__ __align__(16) int   g_off[NN];
__device__ __align__(16) int   g_cur[NN];
__device__ int g_total;
__device__ int g_is64;

__device__ __align__(16) uint2 g_edge[NE];      // CSR: {src, fp32 w=dinv[src]*ea}

__device__ __align__(16) __half g_t1h[NN * 32]; // x @ W1 (fp16)
__device__ __align__(16) __half g_h1h[NN * 32]; // elu layer-1 out (fp16)
__device__ __align__(16) __half g_h2h[NN * 64]; // elu layer-2 out (fp16)

// ---------------- packed f32x2 helpers --------------------------------------
__device__ __forceinline__ unsigned long long pack_f32x2(float lo, float hi) {
    unsigned long long r;
    asm("mov.b64 %0, {%1, %2};" : "=l"(r) : "f"(lo), "f"(hi));
    return r;
}
__device__ __forceinline__ void unpack_f32x2(unsigned long long v,
                                             float& lo, float& hi) {
    asm("mov.b64 {%0, %1}, %2;" : "=f"(lo), "=f"(hi) : "l"(v));
}
__device__ __forceinline__ void fma_f32x2(unsigned long long& d,
                                          unsigned long long a,
                                          unsigned long long b) {
    asm("fma.rn.f32x2 %0, %1, %2, %0;" : "+l"(d) : "l"(a), "l"(b));
}

// ---------------- dtype detect (1 block) ------------------------------------
__global__ void k_detect(const int* __restrict__ ei32) {
    __shared__ int cnt;
    if (threadIdx.x == 0) { cnt = 0; g_total = 0; }
    __syncthreads();
    int zeros = 0;
    for (int i = threadIdx.x; i < 1024; i += blockDim.x)
        if (ei32[2 * i + 1] == 0) zeros++;
    atomicAdd(&cnt, zeros);
    __syncthreads();
    if (threadIdx.x == 0) g_is64 = (cnt > 900) ? 1 : 0;
}

__device__ __forceinline__ void load_edge(const int* __restrict__ ei32,
                                          int e, int E, int n, int& r, int& c) {
    if (g_is64) {
        r = ei32[2 * (long long)e];
        c = ei32[2 * ((long long)E + e)];
    } else {
        r = ei32[e];
        c = ei32[E + e];
    }
    if ((unsigned)r >= (unsigned)n) r = 0;
    if ((unsigned)c >= (unsigned)n) c = 0;
}

__global__ void k_prep(const int* __restrict__ ei32,
                       const float* __restrict__ ea, int E, int n) {
    int e = blockIdx.x * blockDim.x + threadIdx.x;
    if (e >= E) return;
    int c;
    if (g_is64) c = ei32[2 * ((long long)E + e)];
    else        c = ei32[E + e];
    if ((unsigned)c >= (unsigned)n) c = 0;
    const unsigned long long add =
        (1ULL << 40) | (unsigned long long)(fmaxf(ea[e], 0.f) * DEG_SCALE + 0.5f);
    atomicAdd(&g_pack[c], add);
}

// ---------------- assign: dinv decode + counter-based segment reservation ---
__global__ void k_assign(int n) {
    int i = blockIdx.x * blockDim.x + threadIdx.x;
    if (i >= n) return;
    const unsigned long long p = g_pack[i];
    g_pack[i] = 0ULL;                              // restore invariant
    const int cnt = (int)(p >> 40);
    g_cnt[i] = cnt;
    const float d = 1.0f + (float)(p & 0xFFFFFFFFFFULL) * (1.0f / DEG_SCALE);
    g_dinv[i] = rsqrtf(d);
    const int pos = atomicAdd(&g_total, cnt);
    g_off[i] = pos;
    g_cur[i] = pos;
}

// ---------------- CSR fill: w = dinv[src]*ea (dst factor applied in agg) ---
__global__ void k_fill(const int* __restrict__ ei32,
                       const float* __restrict__ ea, int E, int n) {
    int e = blockIdx.x * blockDim.x + threadIdx.x;
    if (e >= E) return;
    int r, c;
    load_edge(ei32, e, E, n, r, c);
    const int pos = atomicAdd(&g_cur[c], 1);
    const float w = g_dinv[r] * ea[e];
    g_edge[pos] = make_uint2((unsigned)r, __float_as_uint(w));
}

// ---------------- agg gather core (8 fp32 accumulators per thread) ---------
// Aggregates segment of `node`, lane-slice s (8 halfs), applies dinv scaling
// and self-loop. Results left in a[0..7].
__device__ __forceinline__ void agg_core(const __half* __restrict__ gh, int F,
                                         int node, int s, float* a) {
    const __half* __restrict__ tbl = gh + s * 8;
    const int base = g_off[node];
    const int deg  = g_cnt[node];
#define GATH(ED)                                                               \
    {                                                                          \
        const float w_ = __uint_as_float((ED).y);                              \
        const uint4 raw_ = *(const uint4*)(tbl + (size_t)(ED).x * F);          \
        const float2 p0_ = __half22float2(*(const __half2*)&raw_.x);           \
        const float2 p1_ = __half22float2(*(const __half2*)&raw_.y);           \
        const float2 p2_ = __half22float2(*(const __half2*)&raw_.z);           \
        const float2 p3_ = __half22float2(*(const __half2*)&raw_.w);           \
        a[0] += p0_.x * w_; a[1] += p0_.y * w_;                                \
        a[2] += p1_.x * w_; a[3] += p1_.y * w_;                                \
        a[4] += p2_.x * w_; a[5] += p2_.y * w_;                                \
        a[6] += p3_.x * w_; a[7] += p3_.y * w_;                                \
    }
    int k = 0;
    for (; k + 4 <= deg; k += 4) {
        const uint2 e0 = g_edge[base + k],     e1 = g_edge[base + k + 1];
        const uint2 e2 = g_edge[base + k + 2], e3 = g_edge[base + k + 3];
        GATH(e0) GATH(e1) GATH(e2) GATH(e3)
    }
    for (; k < deg; k++) {
        const uint2 e0 = g_edge[base + k];
        GATH(e0)
    }
#undef GATH
    const float dn = g_dinv[node];
    const uint4 raw = *(const uint4*)(tbl + (size_t)node * F);
    const float2 p0 = __half22float2(*(const __half2*)&raw.x);
    const float2 p1 = __half22float2(*(const __half2*)&raw.y);
    const float2 p2 = __half22float2(*(const __half2*)&raw.z);
    const float2 p3 = __half22float2(*(const __half2*)&raw.w);
    a[0] = (a[0] + p0.x * dn) * dn; a[1] = (a[1] + p0.y * dn) * dn;
    a[2] = (a[2] + p1.x * dn) * dn; a[3] = (a[3] + p1.y * dn) * dn;
    a[4] = (a[4] + p2.x * dn) * dn; a[5] = (a[5] + p2.y * dn) * dn;
    a[6] = (a[6] + p3.x * dn) * dn; a[7] = (a[7] + p3.y * dn) * dn;
}

// ---------------- standalone agg (layer 1): fp16 out, bias+elu -------------
template <int F>
__global__ void k_agg(const __half* __restrict__ gh, const float* __restrict__ b,
                      __half* __restrict__ outh, int n) {
    constexpr int LPE = F / 8;
    const long long tid = (long long)blockIdx.x * blockDim.x + threadIdx.x;
    const int node = (int)(tid / LPE);
    const int s = (int)(tid % LPE);
    if (node >= n) return;

    float a[8] = {0.f, 0.f, 0.f, 0.f, 0.f, 0.f, 0.f, 0.f};
    agg_core(gh, F, node, s, a);
#pragma unroll
    for (int j = 0; j < 8; j++) {
        float v = a[j] + b[s * 8 + j];
        a[j] = (v > 0.f) ? v : expm1f(v);
    }
    __half2* hp = (__half2*)(outh + (size_t)node * F + s * 8);
    hp[0] = __floats2half2_rn(a[0], a[1]);
    hp[1] = __floats2half2_rn(a[2], a[3]);
    hp[2] = __floats2half2_rn(a[4], a[5]);
    hp[3] = __floats2half2_rn(a[6], a[7]);
}

// ---------------- fused agg + GEMM: h_out = [elu]( (A gh) @ W + b ) ---------
// Phase A: block aggregates NPB nodes into smem Xs (transposed, fp32).
// Phase B: register-tiled f32x2 GEMM on Xs; fused bias/ELU epilogue.
// Geometry: LPE=FIN/8 lanes/node -> NPB=256/LPE nodes/block == BY*4 (checked).
template <int FIN, int FOUT, bool ELU, bool OUTF>
__global__ void k_aggemm(const __half* __restrict__ gh,
                         const float* __restrict__ W,
                         const float* __restrict__ b,
                         float* __restrict__ Yf, __half* __restrict__ Yh,
                         int n) {
    constexpr int LPE  = FIN / 8;
    constexpr int NPB  = 256 / LPE;
    constexpr int BX   = FOUT / 4;
    constexpr int BY   = 256 / BX;
    constexpr int KC   = 32;
    constexpr int XSTR = NPB + 1;
    static_assert(BY * 4 == NPB, "geometry mismatch");

    __shared__ float Xs[FIN * XSTR];
    __shared__ float Ws[KC * FOUT];

    const int tid = threadIdx.x;
    const int node0 = blockIdx.x * NPB;

    // ---- Phase A: aggregate into Xs (transposed) ----
    {
        const int ln = tid / LPE;
        const int s  = tid % LPE;
        const int node = node0 + ln;
        float a[8] = {0.f, 0.f, 0.f, 0.f, 0.f, 0.f, 0.f, 0.f};
        if (node < n) agg_core(gh, FIN, node, s, a);
#pragma unroll
        for (int j = 0; j < 8; j++)
            Xs[(s * 8 + j) * XSTR + ln] = a[j];
    }
    __syncthreads();

    // ---- Phase B: register-tiled GEMM from smem ----
    const int tx = tid % BX;
    const int ty = tid / BX;

    unsigned long long acc01[4] = {0ULL, 0ULL, 0ULL, 0ULL};
    unsigned long long acc23[4] = {0ULL, 0ULL, 0ULL, 0ULL};

    for (int ck = 0; ck < FIN; ck += KC) {
#pragma unroll
        for (int t = 0; t < KC * FOUT / 256; t++) {
            const int idx = t * 256 + tid;
            Ws[idx] = W[(size_t)(ck + idx / FOUT) * FOUT + (idx % FOUT)];
        }
        __syncthreads();

#pragma unroll
        for (int k = 0; k < KC; k++) {
            const ulonglong2 wp = *(const ulonglong2*)&Ws[k * FOUT + tx * 4];
#pragma unroll
            for (int j = 0; j < 4; j++) {
                const float xv = Xs[(ck + k) * XSTR + ty * 4 + j];
                const unsigned long long xx = pack_f32x2(xv, xv);
                fma_f32x2(acc01[j], xx, wp.x);
                fma_f32x2(acc23[j], xx, wp.y);
            }
        }
        __syncthreads();
    }

    const float4 bv = *(const float4*)&b[tx * 4];

#pragma unroll
    for (int j = 0; j < 4; j++) {
        const int node = node0 + ty * 4 + j;
        if (node >= n) continue;
        float o0, o1, o2, o3;
        unpack_f32x2(acc01[j], o0, o1);
        unpack_f32x2(acc23[j], o2, o3);
        o0 += bv.x; o1 += bv.y; o2 += bv.z; o3 += bv.w;
        if (ELU) {
            o0 = (o0 > 0.f) ? o0 : expm1f(o0);
            o1 = (o1 > 0.f) ? o1 : expm1f(o1);
            o2 = (o2 > 0.f) ? o2 : expm1f(o2);
            o3 = (o3 > 0.f) ? o3 : expm1f(o3);
        }
        if (OUTF) {
            float4 ov; ov.x = o0; ov.y = o1; ov.z = o2; ov.w = o3;
            *(float4*)(Yf + (size_t)node * FOUT + tx * 4) = ov;
        } else {
            __half2* hp = (__half2*)(Yh + (size_t)node * FOUT + tx * 4);
            hp[0] = __floats2half2_rn(o0, o1);
            hp[1] = __floats2half2_rn(o2, o3);
        }
    }
}

// ---------------- standalone GEMM (layer 1, x fp32 -> t1h fp16) ------------
template <int FIN, int FOUT>
__global__ void k_gemm1(const float* __restrict__ X, const float* __restrict__ W,
                        __half* __restrict__ Yh, int n) {
    constexpr int BX   = FOUT / 4;
    constexpr int BY   = 256 / BX;
    constexpr int NPB  = BY * 4;
    constexpr int KC   = 32;
    constexpr int XSTR = NPB + 1;

    __shared__ float Xs[KC * XSTR];
    __shared__ float Ws[KC * FOUT];

    const int tid = threadIdx.x;
    const int tx = tid % BX;
    const int ty = tid / BX;
    const int node0 = blockIdx.x * NPB;

    unsigned long long acc01[4] = {0ULL, 0ULL, 0ULL, 0ULL};
    unsigned long long acc23[4] = {0ULL, 0ULL, 0ULL, 0ULL};

    for (int ck = 0; ck < FIN; ck += KC) {
#pragma unroll
        for (int t = 0; t < NPB * KC / 256; t++) {
            const int idx = t * 256 + tid;
            const int ln = idx / KC;
            const int k  = idx % KC;
            const int node = node0 + ln;
            Xs[k * XSTR + ln] = (node < n) ? X[(size_t)node * FIN + ck + k] : 0.f;
        }
#pragma unroll
        for (int t = 0; t < KC * FOUT / 256; t++) {
            const int idx = t * 256 + tid;
            Ws[idx] = W[(size_t)(ck + idx / FOUT) * FOUT + (idx % FOUT)];
        }
        __syncthreads();

#pragma unroll
        for (int k = 0; k < KC; k++) {
            const ulonglong2 wp = *(const ulonglong2*)&Ws[k * FOUT + tx * 4];
#pragma unroll
            for (int j = 0; j < 4; j++) {
                const float xv = Xs[k * XSTR + ty * 4 + j];
                const unsigned long long xx = pack_f32x2(xv, xv);
                fma_f32x2(acc01[j], xx, wp.x);
                fma_f32x2(acc23[j], xx, wp.y);
            }
        }
        __syncthreads();
    }

#pragma unroll
    for (int j = 0; j < 4; j++) {
        const int node = node0 + ty * 4 + j;
        if (node >= n) continue;
        float o0, o1, o2, o3;
        unpack_f32x2(acc01[j], o0, o1);
        unpack_f32x2(acc23[j], o2, o3);
        __half2* hp = (__half2*)(Yh + (size_t)node * FOUT + tx * 4);
        hp[0] = __floats2half2_rn(o0, o1);
        hp[1] = __floats2half2_rn(o2, o3);
    }
}

// ---------------- launch ---------------------------------------------------
static inline int cdiv(long long a, int b) { return (int)((a + b - 1) / b); }

// Lazy-created side stream + events (host resources only; no device memory).
static cudaStream_t s_side = nullptr;
static cudaEvent_t  s_evFork = nullptr, s_evJoin = nullptr;

extern "C" void kernel_launch(void* const* d_in, const int* in_sizes, int n_in,
                              void* d_out, int out_size) {
    const float* x  = (const float*)d_in[0];
    const int*   ei = (const int*)d_in[1];
    const float* ea = (const float*)d_in[2];
    const float* W1 = (const float*)d_in[3];
    const float* b1 = (const float*)d_in[4];
    const float* W2 = (const float*)d_in[5];
    const float* b2 = (const float*)d_in[6];
    const float* W3 = (const float*)d_in[7];
    const float* b3 = (const float*)d_in[8];
    float* out = (float*)d_out;

    const int n = in_sizes[0] / 128;   // 100000
    const int E = in_sizes[2];         // 3200000

    if (s_side == nullptr) {
        cudaStreamCreateWithFlags(&s_side, cudaStreamNonBlocking);
        cudaEventCreateWithFlags(&s_evFork, cudaEventDisableTiming);
        cudaEventCreateWithFlags(&s_evJoin, cudaEventDisableTiming);
    }

    void *p_t1h, *p_h1h, *p_h2h;
    cudaGetSymbolAddress(&p_t1h, g_t1h);
    cudaGetSymbolAddress(&p_h1h, g_h1h);
    cudaGetSymbolAddress(&p_h2h, g_h2h);

    const int T = 256;

    // --- fork: GEMM1 (x@W1, independent of CSR prep) on side stream ---
    cudaEventRecord(s_evFork, 0);
    cudaStreamWaitEvent(s_side, s_evFork, 0);
    k_gemm1<128, 32><<<cdiv(n, 128), 256, 0, s_side>>>(
        x, W1, (__half*)p_t1h, n);
    cudaEventRecord(s_evJoin, s_side);

    // --- prep: detect, degree atomics, offsets, CSR fill (main stream) ---
    k_detect<<<1, 256>>>(ei);
    k_prep<<<cdiv(E, T), T>>>(ei, ea, E, n);
    k_assign<<<cdiv(n, T), T>>>(n);
    k_fill<<<cdiv(E, T), T>>>(ei, ea, E, n);

    // --- join: layer-1 agg needs both t1h (side) and CSR (main) ---
    cudaStreamWaitEvent(0, s_evJoin, 0);
    k_agg<32><<<cdiv((long long)n * 4, T), T>>>(
        (const __half*)p_t1h, b1, (__half*)p_h1h, n);

    // --- layer 2 fused: h2 = elu( (A h1) @ W2 + b2 ) ---
    k_aggemm<32, 64, true, false><<<cdiv(n, 64), 256>>>(
        (const __half*)p_h1h, W2, b2, nullptr, (__half*)p_h2h, n);

    // --- layer 3 fused: out = (A h2) @ W3 + b3 ---
    k_aggemm<64, 128, false, true><<<cdiv(n, 32), 256>>>(
        (const __half*)p_h2h, W3, b3, out, nullptr, n);
}